// round 9
// baseline (speedup 1.0000x reference)
#include <cuda_runtime.h>
#include <cuda_bf16.h>
#include <cstdint>

#define DI __device__ __forceinline__
constexpr int N_=2048, D_=512, MR=4096, WE=262144;

__device__ __nv_bfloat16 g_xnh[MR*D_],g_xnl[MR*D_],g_cnh[MR*D_],g_cnl[MR*D_];
__device__ __nv_bfloat16 g_qkh[MR*D_],g_qkl[MR*D_],g_ckh[MR*D_],g_ckl[MR*D_];
__device__ __nv_bfloat16 g_vth[MR*D_],g_vtl[MR*D_],g_cvh[MR*D_],g_cvl[MR*D_];
__device__ __nv_bfloat16 g_oh[MR*D_],g_ol[MR*D_],g_gh[MR*D_],g_gl[MR*D_];
__device__ __nv_bfloat16 g_wh[6*WE],g_wl[6*WE];

DI uint32_t s2u(const void* p){uint32_t a;asm("{ .reg .u64 t; cvta.to.shared.u64 t,%1; cvt.u32.u64 %0,t; }":"=r"(a):"l"(p));return a;}
DI void ldm4(uint32_t* r,uint32_t a){
    asm volatile("ldmatrix.sync.aligned.m8n8.x4.shared.b16 {%0,%1,%2,%3},[%4];"
        :"=r"(r[0]),"=r"(r[1]),"=r"(r[2]),"=r"(r[3]):"r"(a));
}
DI void ldm2(uint32_t* r,uint32_t a){
    asm volatile("ldmatrix.sync.aligned.m8n8.x2.shared.b16 {%0,%1},[%2];"
        :"=r"(r[0]),"=r"(r[1]):"r"(a));
}
DI void hmma(float* c,const uint32_t* a,const uint32_t* b){
    asm volatile("mma.sync.aligned.m16n8k16.row.col.f32.bf16.bf16.f32 {%0,%1,%2,%3},{%4,%5,%6,%7},{%8,%9},{%0,%1,%2,%3};"
        :"+f"(c[0]),"+f"(c[1]),"+f"(c[2]),"+f"(c[3])
        :"r"(a[0]),"r"(a[1]),"r"(a[2]),"r"(a[3]),"r"(b[0]),"r"(b[1]));
}
DI void cpa(uint32_t d,const void* s){asm volatile("cp.async.cg.shared.global [%0],[%1],16;"::"r"(d),"l"(s));}

DI float fexp(float x){
    x=fmaxf(x,-80.f); float t=x*1.4426950408889634f;
    float z=t+12582912.f, fi=z-12582912.f, f=t-fi;
    int i=__float_as_int(z)-0x4B400000;
    float p=1.3333558146428443e-3f;
    p=fmaf(p,f,9.618129107628477e-3f); p=fmaf(p,f,5.550410866482158e-2f);
    p=fmaf(p,f,2.402265069591007e-1f); p=fmaf(p,f,6.931471805599453e-1f);
    p=fmaf(p,f,1.0f);
    return __int_as_float(__float_as_int(p)+(i<<23));
}
DI void spl(float v,__nv_bfloat16&h,__nv_bfloat16&l){h=__float2bfloat16(v);l=__float2bfloat16(v-__bfloat162float(h));}
DI uint32_t pk2(__nv_bfloat16 a,__nv_bfloat16 b){return ((uint32_t)__bfloat16_as_ushort(b)<<16)|(uint32_t)__bfloat16_as_ushort(a);}

DI float wred(float v){
    #pragma unroll
    for(int o=16;o>0;o>>=1)v+=__shfl_xor_sync(0xffffffffu,v,o);
    return v;
}
__global__ void ln_k(const float* __restrict__ x,const float* __restrict__ g,const float* __restrict__ b,int which){
    __shared__ float sh[8];
    long row=blockIdx.x;
    float4 v=((const float4*)(x+row*D_))[threadIdx.x];
    float s=v.x+v.y+v.z+v.w, sq=v.x*v.x+v.y*v.y+v.z*v.z+v.w*v.w;
    int l=threadIdx.x&31,w=threadIdx.x>>5;
    s=wred(s);sq=wred(sq);
    if(l==0){sh[w]=s;sh[4+w]=sq;}
    __syncthreads();
    s=sh[0]+sh[1]+sh[2]+sh[3]; sq=sh[4]+sh[5]+sh[6]+sh[7];
    float mu=s/D_, rstd=rsqrtf(sq/D_-mu*mu+1e-5f);
    float4 gg=((const float4*)g)[threadIdx.x], bb=((const float4*)b)[threadIdx.x];
    float o0=(v.x-mu)*rstd*gg.x+bb.x, o1=(v.y-mu)*rstd*gg.y+bb.y;
    float o2=(v.z-mu)*rstd*gg.z+bb.z, o3=(v.w-mu)*rstd*gg.w+bb.w;
    __nv_bfloat16 h0,h1,h2,h3,l0,l1,l2,l3;
    spl(o0,h0,l0);spl(o1,h1,l1);spl(o2,h2,l2);spl(o3,h3,l3);
    __nv_bfloat16* dh=which?g_cnh:g_xnh; __nv_bfloat16* dl=which?g_cnl:g_xnl;
    long a=row*D_+threadIdx.x*4;
    *(uint2*)(dh+a)=make_uint2(pk2(h0,h1),pk2(h2,h3));
    *(uint2*)(dl+a)=make_uint2(pk2(l0,l1),pk2(l2,l3));
}
__global__ void wsplit_k(const float* w0,const float* w1,const float* w2,const float* w3,const float* w4,const float* w5){
    __shared__ float t[32][33];
    int z=blockIdx.z;
    const float* W=(z==0)?w0:(z==1)?w1:(z==2)?w2:(z==3)?w3:(z==4)?w4:w5;
    int n0=blockIdx.x*32,k0=blockIdx.y*32,tx=threadIdx.x,ty=threadIdx.y;
    t[ty][tx]=W[(long)(k0+ty)*512+n0+tx];
    __syncthreads();
    float v=t[tx][ty];
    long a=(long)z*WE+(long)(n0+ty)*512+k0+tx;
    __nv_bfloat16 h,l;spl(v,h,l); g_wh[a]=h;g_wl[a]=l;
}

// MODE 0: input projections (z: 0 qk,1 cqk,2 v,3 cv)   MODE 4: final proj
template<int MODE>
__global__ void __launch_bounds__(256) mm_k(float* outp,const float* bi0,const float* bi1){
    extern __shared__ __align__(16) char sm[];
    constexpr int NCH=16;
    constexpr int BSZ=128*80;
    constexpr int BUF=20480+2*BSZ;
    uint32_t sb=s2u(sm);
    int tid=threadIdx.x,w=tid>>5,l=tid&31,z=blockIdx.z;
    int m0=blockIdx.y*128, n0=blockIdx.x*128;
    int wm0=(w>>2)*64, wn0=(w&3)*32;

    const __nv_bfloat16 *Ah,*Al,*Bh,*Bl;
    if(MODE==0){
        Ah=((z&1)?g_cnh:g_xnh)+(long)m0*512; Al=((z&1)?g_cnl:g_xnl)+(long)m0*512;
        Bh=g_wh+(long)z*WE+(long)n0*512; Bl=g_wl+(long)z*WE+(long)n0*512;
    } else {
        Ah=(z?g_gh:g_oh)+(long)m0*512; Al=(z?g_gl:g_ol)+(long)m0*512;
        Bh=g_wh+(long)(4+z)*WE+(long)n0*512; Bl=g_wl+(long)(4+z)*WE+(long)n0*512;
    }
    float acc[4][4][4];
    #pragma unroll
    for(int i=0;i<4;i++)
        #pragma unroll
        for(int j=0;j<4;j++)
            #pragma unroll
            for(int e=0;e<4;e++)acc[i][j][e]=0.f;

    auto issue=[&](int kc){
        uint32_t bs=sb+(uint32_t)(kc&1)*BUF;
        const __nv_bfloat16* a=Ah+kc*32; const __nv_bfloat16* a2=Al+kc*32;
        for(int c=tid;c<512;c+=256){int r=c>>2,q=c&3;
            cpa(bs+r*80+q*16,a+(long)r*512+q*8);
            cpa(bs+10240+r*80+q*16,a2+(long)r*512+q*8);}
        const __nv_bfloat16* b=Bh+kc*32; const __nv_bfloat16* b2=Bl+kc*32;
        for(int c=tid;c<512;c+=256){int r=c>>2,q=c&3;
            cpa(bs+20480+r*80+q*16,b+(long)r*512+q*8);
            cpa(bs+20480+BSZ+r*80+q*16,b2+(long)r*512+q*8);}
        asm volatile("cp.async.commit_group;");
    };

    issue(0);
    for(int kc=0;kc<NCH;++kc){
        if(kc+1<NCH){issue(kc+1); asm volatile("cp.async.wait_group 1;");}
        else asm volatile("cp.async.wait_group 0;");
        __syncthreads();
        uint32_t bs=sb+(uint32_t)(kc&1)*BUF;
        uint32_t fbh[4][4],fbl[4][4];
        #pragma unroll
        for(int ni=0;ni<4;++ni){
            uint32_t ba=bs+20480+(uint32_t)((wn0+ni*8+(l&7))*80+(l>>3)*16);
            ldm4(fbh[ni],ba); ldm4(fbl[ni],ba+BSZ);
        }
        #pragma unroll
        for(int kk=0;kk<2;++kk){
            uint32_t fa[4][4];
            #pragma unroll
            for(int mi=0;mi<4;++mi)
                ldm4(fa[mi],bs+(uint32_t)((wm0+mi*16+(l&15))*80+kk*32+(l>>4)*16));
            #pragma unroll
            for(int mi=0;mi<4;++mi)
                #pragma unroll
                for(int ni=0;ni<4;++ni){
                    hmma(acc[mi][ni],fa[mi],&fbh[ni][kk*2]);
                    hmma(acc[mi][ni],fa[mi],&fbl[ni][kk*2]);
                }
            #pragma unroll
            for(int mi=0;mi<4;++mi)
                ldm4(fa[mi],bs+10240+(uint32_t)((wm0+mi*16+(l&15))*80+kk*32+(l>>4)*16));
            #pragma unroll
            for(int mi=0;mi<4;++mi)
                #pragma unroll
                for(int ni=0;ni<4;++ni)
                    hmma(acc[mi][ni],fa[mi],&fbh[ni][kk*2]);
        }
        __syncthreads();
    }

    int g=l>>2,t=l&3;
    if(MODE==0){
        float sc=(z==0)?0.125f:1.f;
        if(z<2){
            __nv_bfloat16* dh=z?g_ckh:g_qkh; __nv_bfloat16* dl=z?g_ckl:g_qkl;
            #pragma unroll
            for(int mi=0;mi<4;++mi)
                #pragma unroll
                for(int h2=0;h2<2;++h2){
                    int row=wm0+mi*16+g+h2*8;
                    long a=(long)(m0+row)*512+n0;
                    #pragma unroll
                    for(int ni=0;ni<4;++ni){
                        float v0=acc[mi][ni][h2*2]*sc, v1=acc[mi][ni][h2*2+1]*sc;
                        __nv_bfloat16 h0,lo0,h1,lo1; spl(v0,h0,lo0); spl(v1,h1,lo1);
                        int col=wn0+ni*8+2*t;
                        *(uint32_t*)(dh+a+col)=pk2(h0,h1);
                        *(uint32_t*)(dl+a+col)=pk2(lo0,lo1);
                    }
                }
        } else {
            __nv_bfloat16* dh=(z==2)?g_vth:g_cvh; __nv_bfloat16* dl=(z==2)?g_vtl:g_cvl;
            #pragma unroll
            for(int mi=0;mi<4;++mi)
                #pragma unroll
                for(int e=0;e<4;++e){
                    int row=m0+wm0+mi*16+g+(e>>1)*8;
                    int bb=row>>11, ii=row&2047;
                    #pragma unroll
                    for(int ni=0;ni<4;++ni){
                        int inner=n0+wn0+ni*8+2*t+(e&1);
                        long a=((long)((bb*8+(inner>>6))*64+(inner&63)))*N_+ii;
                        float v=acc[mi][ni][e];
                        __nv_bfloat16 h,lo;spl(v,h,lo);
                        dh[a]=h; dl[a]=lo;
                    }
                }
        }
    } else {
        const float* bias=z?bi1:bi0;
        #pragma unroll
        for(int mi=0;mi<4;++mi)
            #pragma unroll
            for(int h2=0;h2<2;++h2){
                int row=wm0+mi*16+g+h2*8;
                float* dst=outp+((long)z*MR+m0+row)*512+n0;
                #pragma unroll
                for(int ni=0;ni<4;++ni){
                    int col=wn0+ni*8+2*t;
                    float2 v;
                    v.x=acc[mi][ni][h2*2]+bias[n0+col];
                    v.y=acc[mi][ni][h2*2+1]+bias[n0+col+1];
                    *(float2*)(dst+col)=v;
                }
            }
    }
}

// ---------------- symmetric flash attention (one direction per launch) ------
// Q tile [128 x 64] fixed; loop 32 tiles of K [64 x 64] and V d-major [64 x 64].
// All rows stride 144B. E [128 x 64] hi+lo in smem. out acc + rowsum in regs.
constexpr int FQ=0;        // hi; lo at +18432        (2*18432)
constexpr int FK=36864;    // hi; lo at +9216         (2*9216)
constexpr int FV=55296;    // hi; lo at +9216         (2*9216)
constexpr int FE=73728;    // hi; lo at +18432        (2*18432)
constexpr int FR=110592;   // float[128]
constexpr int SMF2=111104;

__global__ void __launch_bounds__(256,2) fused2(
    const __nv_bfloat16* __restrict__ Qh,const __nv_bfloat16* __restrict__ Ql,
    const __nv_bfloat16* __restrict__ Kh,const __nv_bfloat16* __restrict__ Kl,
    const __nv_bfloat16* __restrict__ Vh,const __nv_bfloat16* __restrict__ Vl,
    __nv_bfloat16* __restrict__ Oh,__nv_bfloat16* __restrict__ Ol)
{
    extern __shared__ __align__(16) char sm[];
    uint32_t sb=s2u(sm);
    int tid=threadIdx.x,w=tid>>5,l=tid&31;
    int it=blockIdx.x, z=blockIdx.y, bq=z>>3, hq=z&7;
    int i0=it*128;
    long qoff=((long)(bq*2048+i0))*512+hq*64;
    long kbase=((long)(bq*2048))*512+hq*64;
    long vbase=(long)z*64*2048;
    float* srow=(float*)(sm+FR);
    if(tid<128) srow[tid]=0.f;

    // Q tile (joins group A with K0)
    for(int c=tid;c<1024;c+=256){int r=c>>3,q=c&7;
        cpa(sb+FQ+r*144+q*16,       Qh+qoff+(long)r*512+q*8);
        cpa(sb+FQ+18432+r*144+q*16, Ql+qoff+(long)r*512+q*8);}
    auto issue_k=[&](int jc){
        for(int c=tid;c<512;c+=256){int r=c>>3,q=c&7;
            cpa(sb+FK+r*144+q*16,      Kh+kbase+(long)(jc*64+r)*512+q*8);
            cpa(sb+FK+9216+r*144+q*16, Kl+kbase+(long)(jc*64+r)*512+q*8);}
        asm volatile("cp.async.commit_group;");
    };
    auto issue_v=[&](int jc){
        for(int c=tid;c<512;c+=256){int r=c>>3,q=c&7;
            cpa(sb+FV+r*144+q*16,      Vh+vbase+(long)r*2048+jc*64+q*8);
            cpa(sb+FV+9216+r*144+q*16, Vl+vbase+(long)r*2048+jc*64+q*8);}
        asm volatile("cp.async.commit_group;");
    };
    issue_k(0); issue_v(0);

    int g=l>>2,t=l&3;
    int wm=(w>>1)*32, wn=(w&1)*32;
    float acc_o[2][4][4]; float rsum[2][2];
    #pragma unroll
    for(int i=0;i<2;i++)
        #pragma unroll
        for(int j=0;j<4;j++)
            #pragma unroll
            for(int e=0;e<4;e++)acc_o[i][j][e]=0.f;
    rsum[0][0]=rsum[0][1]=rsum[1][0]=rsum[1][1]=0.f;

    for(int jc=0;jc<32;++jc){
        asm volatile("cp.async.wait_group 1;");   // K(jc) (+Q at jc=0)
        __syncthreads();
        // ---- sim: Q(split) x K(split), 3 products, K=64 ----
        float s[2][4][4];
        #pragma unroll
        for(int i=0;i<2;i++)
            #pragma unroll
            for(int j=0;j<4;j++)
                #pragma unroll
                for(int e=0;e<4;e++)s[i][j][e]=0.f;
        #pragma unroll
        for(int kk=0;kk<4;++kk){
            uint32_t fbh[4][2],fbl[4][2];
            #pragma unroll
            for(int ni=0;ni<4;++ni){
                uint32_t ba=sb+FK+(uint32_t)((wn+ni*8+(l&7))*144+kk*32+((l>>3)&1)*16);
                ldm2(fbh[ni],ba); ldm2(fbl[ni],ba+9216);
            }
            uint32_t fa[2][4];
            #pragma unroll
            for(int mi=0;mi<2;++mi)
                ldm4(fa[mi],sb+FQ+(uint32_t)((wm+mi*16+(l&15))*144+kk*32+(l>>4)*16));
            #pragma unroll
            for(int mi=0;mi<2;++mi)
                #pragma unroll
                for(int ni=0;ni<4;++ni){
                    hmma(s[mi][ni],fa[mi],fbh[ni]);
                    hmma(s[mi][ni],fa[mi],fbl[ni]);
                }
            #pragma unroll
            for(int mi=0;mi<2;++mi)
                ldm4(fa[mi],sb+FQ+18432+(uint32_t)((wm+mi*16+(l&15))*144+kk*32+(l>>4)*16));
            #pragma unroll
            for(int mi=0;mi<2;++mi)
                #pragma unroll
                for(int ni=0;ni<4;++ni)
                    hmma(s[mi][ni],fa[mi],fbh[ni]);
        }
        // ---- exp -> E smem (hi+lo), rowsum in regs ----
        #pragma unroll
        for(int mi=0;mi<2;++mi)
            #pragma unroll
            for(int h2=0;h2<2;++h2){
                float rp=0.f;
                int row=wm+mi*16+g+h2*8;
                #pragma unroll
                for(int ni=0;ni<4;++ni){
                    float e0=fexp(s[mi][ni][h2*2]), e1=fexp(s[mi][ni][h2*2+1]);
                    rp+=e0+e1;
                    __nv_bfloat16 h0,lo0,h1,lo1; spl(e0,h0,lo0); spl(e1,h1,lo1);
                    int cb=row*144+(wn+ni*8+2*t)*2;
                    *(uint32_t*)(sm+FE+cb)=pk2(h0,h1);
                    *(uint32_t*)(sm+FE+18432+cb)=pk2(lo0,lo1);
                }
                rp+=__shfl_xor_sync(0xffffffffu,rp,1);
                rp+=__shfl_xor_sync(0xffffffffu,rp,2);
                rsum[mi][h2]+=rp;
            }
        __syncthreads();                           // E ready; K consumed
        if(jc+1<32){ issue_k(jc+1); asm volatile("cp.async.wait_group 1;"); }
        else asm volatile("cp.async.wait_group 0;");
        __syncthreads();                           // V(jc) visible
        // ---- out: acc_o += Eh@(Vh+Vl) + El@Vh, K=64 ----
        #pragma unroll
        for(int kk=0;kk<4;++kk){
            uint32_t gbh[4][2],gbl[4][2];
            #pragma unroll
            for(int ni=0;ni<4;++ni){
                uint32_t ba=sb+FV+(uint32_t)((wn+ni*8+(l&7))*144+kk*32+((l>>3)&1)*16);
                ldm2(gbh[ni],ba); ldm2(gbl[ni],ba+9216);
            }
            uint32_t fe[2][4];
            #pragma unroll
            for(int mi=0;mi<2;++mi)
                ldm4(fe[mi],sb+FE+(uint32_t)((wm+mi*16+(l&15))*144+kk*32+(l>>4)*16));
            #pragma unroll
            for(int mi=0;mi<2;++mi)
                #pragma unroll
                for(int ni=0;ni<4;++ni){
                    hmma(acc_o[mi][ni],fe[mi],gbh[ni]);
                    hmma(acc_o[mi][ni],fe[mi],gbl[ni]);
                }
            #pragma unroll
            for(int mi=0;mi<2;++mi)
                ldm4(fe[mi],sb+FE+18432+(uint32_t)((wm+mi*16+(l&15))*144+kk*32+(l>>4)*16));
            #pragma unroll
            for(int mi=0;mi<2;++mi)
                #pragma unroll
                for(int ni=0;ni<4;++ni)
                    hmma(acc_o[mi][ni],fe[mi],gbh[ni]);
        }
        __syncthreads();                           // V consumed; E consumed
        if(jc+1<32) issue_v(jc+1);
    }
    // ---- rowsum combine across the 2 n-warps, normalize, split-write ----
    #pragma unroll
    for(int mi=0;mi<2;++mi)
        #pragma unroll
        for(int h2=0;h2<2;++h2)
            if(t==0) atomicAdd(srow+wm+mi*16+g+h2*8,rsum[mi][h2]);
    __syncthreads();
    #pragma unroll
    for(int mi=0;mi<2;++mi)
        #pragma unroll
        for(int h2=0;h2<2;++h2){
            int row=wm+mi*16+g+h2*8;
            float inv=1.f/srow[row];
            long a=((long)(bq*2048+i0+row))*512+hq*64+wn;
            #pragma unroll
            for(int ni=0;ni<4;++ni){
                float v0=acc_o[mi][ni][h2*2]*inv, v1=acc_o[mi][ni][h2*2+1]*inv;
                __nv_bfloat16 h0,lo0,h1,lo1; spl(v0,h0,lo0); spl(v1,h1,lo1);
                *(uint32_t*)(Oh+a+ni*8+2*t)=pk2(h0,h1);
                *(uint32_t*)(Ol+a+ni*8+2*t)=pk2(lo0,lo1);
            }
        }
}

constexpr int SMBIG=2*40960+1024;

extern "C" void kernel_launch(void* const* d_in,const int* in_sizes,int n_in,void* d_out,int out_size){
    (void)in_sizes;(void)n_in;(void)out_size;
    const float* x   =(const float*)d_in[0];
    const float* ctx =(const float*)d_in[1];
    const float* gx  =(const float*)d_in[2];
    const float* bx  =(const float*)d_in[3];
    const float* gc  =(const float*)d_in[4];
    const float* bc  =(const float*)d_in[5];
    const float* Wqk =(const float*)d_in[6];
    const float* Wcqk=(const float*)d_in[7];
    const float* Wv  =(const float*)d_in[8];
    const float* Wcv =(const float*)d_in[9];
    const float* Wout=(const float*)d_in[10];
    const float* bout=(const float*)d_in[11];
    const float* Wco =(const float*)d_in[12];
    const float* bco =(const float*)d_in[13];
    float* out=(float*)d_out;

    __nv_bfloat16 *qkh,*qkl,*ckh,*ckl,*vth,*vtl,*cvh,*cvl,*oh,*ol,*gh,*gl;
    cudaGetSymbolAddress((void**)&qkh,g_qkh); cudaGetSymbolAddress((void**)&qkl,g_qkl);
    cudaGetSymbolAddress((void**)&ckh,g_ckh); cudaGetSymbolAddress((void**)&ckl,g_ckl);
    cudaGetSymbolAddress((void**)&vth,g_vth); cudaGetSymbolAddress((void**)&vtl,g_vtl);
    cudaGetSymbolAddress((void**)&cvh,g_cvh); cudaGetSymbolAddress((void**)&cvl,g_cvl);
    cudaGetSymbolAddress((void**)&oh,g_oh);   cudaGetSymbolAddress((void**)&ol,g_ol);
    cudaGetSymbolAddress((void**)&gh,g_gh);   cudaGetSymbolAddress((void**)&gl,g_gl);

    cudaFuncSetAttribute(mm_k<0>,cudaFuncAttributeMaxDynamicSharedMemorySize,SMBIG);
    cudaFuncSetAttribute(mm_k<4>,cudaFuncAttributeMaxDynamicSharedMemorySize,SMBIG);
    cudaFuncSetAttribute(fused2,cudaFuncAttributeMaxDynamicSharedMemorySize,SMF2);

    ln_k<<<MR,128>>>(x,gx,bx,0);
    ln_k<<<MR,128>>>(ctx,gc,bc,1);
    wsplit_k<<<dim3(16,16,6),dim3(32,32)>>>(Wqk,Wcqk,Wv,Wcv,Wout,Wco);
    mm_k<0><<<dim3(4,32,4),256,SMBIG>>>(nullptr,nullptr,nullptr);
    fused2<<<dim3(16,16),256,SMF2>>>(qkh,qkl,ckh,ckl,cvh,cvl,oh,ol);   // x -> out
    fused2<<<dim3(16,16),256,SMF2>>>(ckh,ckl,qkh,qkl,vth,vtl,gh,gl);   // ctx -> out
    mm_k<4><<<dim3(4,32,2),256,SMBIG>>>(out,bout,bco);
}

// round 10
// speedup vs baseline: 1.0849x; 1.0849x over previous
#include <cuda_runtime.h>
#include <cuda_bf16.h>
#include <cstdint>

#define DI __device__ __forceinline__
constexpr int N_=2048, D_=512, MR=4096, WE=262144;

__device__ __nv_bfloat16 g_xnh[MR*D_],g_xnl[MR*D_],g_cnh[MR*D_],g_cnl[MR*D_];
__device__ __nv_bfloat16 g_qkh[MR*D_],g_qkl[MR*D_],g_ckh[MR*D_],g_ckl[MR*D_];
__device__ __nv_bfloat16 g_vth[MR*D_],g_vtl[MR*D_],g_cvh[MR*D_],g_cvl[MR*D_];
__device__ __nv_bfloat16 g_oh[MR*D_],g_ol[MR*D_],g_gh[MR*D_],g_gl[MR*D_];
__device__ __nv_bfloat16 g_wh[6*WE],g_wl[6*WE];

DI uint32_t s2u(const void* p){uint32_t a;asm("{ .reg .u64 t; cvta.to.shared.u64 t,%1; cvt.u32.u64 %0,t; }":"=r"(a):"l"(p));return a;}
DI void ldm4(uint32_t* r,uint32_t a){
    asm volatile("ldmatrix.sync.aligned.m8n8.x4.shared.b16 {%0,%1,%2,%3},[%4];"
        :"=r"(r[0]),"=r"(r[1]),"=r"(r[2]),"=r"(r[3]):"r"(a));
}
DI void ldm2(uint32_t* r,uint32_t a){
    asm volatile("ldmatrix.sync.aligned.m8n8.x2.shared.b16 {%0,%1},[%2];"
        :"=r"(r[0]),"=r"(r[1]):"r"(a));
}
DI void hmma(float* c,const uint32_t* a,const uint32_t* b){
    asm volatile("mma.sync.aligned.m16n8k16.row.col.f32.bf16.bf16.f32 {%0,%1,%2,%3},{%4,%5,%6,%7},{%8,%9},{%0,%1,%2,%3};"
        :"+f"(c[0]),"+f"(c[1]),"+f"(c[2]),"+f"(c[3])
        :"r"(a[0]),"r"(a[1]),"r"(a[2]),"r"(a[3]),"r"(b[0]),"r"(b[1]));
}
DI void cpa(uint32_t d,const void* s){asm volatile("cp.async.cg.shared.global [%0],[%1],16;"::"r"(d),"l"(s));}

// 64B-row 2-bit swizzle (4 chunks of 16B per row)
DI uint32_t off64(int r,int q){return (uint32_t)(r*64+((q^((r>>1)&3))<<4));}
// 128B-row SW128 swizzle
DI uint32_t swz(uint32_t o){return o^((o>>3)&0x70);}

DI float fexp(float x){
    x=fmaxf(x,-80.f); float t=x*1.4426950408889634f;
    float z=t+12582912.f, fi=z-12582912.f, f=t-fi;
    int i=__float_as_int(z)-0x4B400000;
    float p=1.3333558146428443e-3f;
    p=fmaf(p,f,9.618129107628477e-3f); p=fmaf(p,f,5.550410866482158e-2f);
    p=fmaf(p,f,2.402265069591007e-1f); p=fmaf(p,f,6.931471805599453e-1f);
    p=fmaf(p,f,1.0f);
    return __int_as_float(__float_as_int(p)+(i<<23));
}
DI void spl(float v,__nv_bfloat16&h,__nv_bfloat16&l){h=__float2bfloat16(v);l=__float2bfloat16(v-__bfloat162float(h));}
DI uint32_t pk2(__nv_bfloat16 a,__nv_bfloat16 b){return ((uint32_t)__bfloat16_as_ushort(b)<<16)|(uint32_t)__bfloat16_as_ushort(a);}

DI float wred(float v){
    #pragma unroll
    for(int o=16;o>0;o>>=1)v+=__shfl_xor_sync(0xffffffffu,v,o);
    return v;
}
__global__ void ln_k(const float* __restrict__ x,const float* __restrict__ g,const float* __restrict__ b,int which){
    __shared__ float sh[8];
    long row=blockIdx.x;
    float4 v=((const float4*)(x+row*D_))[threadIdx.x];
    float s=v.x+v.y+v.z+v.w, sq=v.x*v.x+v.y*v.y+v.z*v.z+v.w*v.w;
    int l=threadIdx.x&31,w=threadIdx.x>>5;
    s=wred(s);sq=wred(sq);
    if(l==0){sh[w]=s;sh[4+w]=sq;}
    __syncthreads();
    s=sh[0]+sh[1]+sh[2]+sh[3]; sq=sh[4]+sh[5]+sh[6]+sh[7];
    float mu=s/D_, rstd=rsqrtf(sq/D_-mu*mu+1e-5f);
    float4 gg=((const float4*)g)[threadIdx.x], bb=((const float4*)b)[threadIdx.x];
    float o0=(v.x-mu)*rstd*gg.x+bb.x, o1=(v.y-mu)*rstd*gg.y+bb.y;
    float o2=(v.z-mu)*rstd*gg.z+bb.z, o3=(v.w-mu)*rstd*gg.w+bb.w;
    __nv_bfloat16 h0,h1,h2,h3,l0,l1,l2,l3;
    spl(o0,h0,l0);spl(o1,h1,l1);spl(o2,h2,l2);spl(o3,h3,l3);
    __nv_bfloat16* dh=which?g_cnh:g_xnh; __nv_bfloat16* dl=which?g_cnl:g_xnl;
    long a=row*D_+threadIdx.x*4;
    *(uint2*)(dh+a)=make_uint2(pk2(h0,h1),pk2(h2,h3));
    *(uint2*)(dl+a)=make_uint2(pk2(l0,l1),pk2(l2,l3));
}
__global__ void wsplit_k(const float* w0,const float* w1,const float* w2,const float* w3,const float* w4,const float* w5){
    __shared__ float t[32][33];
    int z=blockIdx.z;
    const float* W=(z==0)?w0:(z==1)?w1:(z==2)?w2:(z==3)?w3:(z==4)?w4:w5;
    int n0=blockIdx.x*32,k0=blockIdx.y*32,tx=threadIdx.x,ty=threadIdx.y;
    t[ty][tx]=W[(long)(k0+ty)*512+n0+tx];
    __syncthreads();
    float v=t[tx][ty];
    long a=(long)z*WE+(long)(n0+ty)*512+k0+tx;
    __nv_bfloat16 h,l;spl(v,h,l); g_wh[a]=h;g_wl[a]=l;
}

// MODE 0: input projections (z: 0 qk,1 cqk,2 v,3 cv)   MODE 4: final proj
// smem per stage: Ah 8K | Al 8K | Bh 8K | Bl 8K = 32K; double-buffered = 64K
template<int MODE>
__global__ void __launch_bounds__(256,2) mm_k(float* outp,const float* bi0,const float* bi1){
    extern __shared__ __align__(16) char sm[];
    constexpr int NCH=16;
    uint32_t sb=s2u(sm);
    int tid=threadIdx.x,w=tid>>5,l=tid&31,z=blockIdx.z;
    int m0=blockIdx.y*128, n0=blockIdx.x*128;
    int wm0=(w>>2)*64, wn0=(w&3)*32;

    const __nv_bfloat16 *Ah,*Al,*Bh,*Bl;
    if(MODE==0){
        Ah=((z&1)?g_cnh:g_xnh)+(long)m0*512; Al=((z&1)?g_cnl:g_xnl)+(long)m0*512;
        Bh=g_wh+(long)z*WE+(long)n0*512; Bl=g_wl+(long)z*WE+(long)n0*512;
    } else {
        Ah=(z?g_gh:g_oh)+(long)m0*512; Al=(z?g_gl:g_ol)+(long)m0*512;
        Bh=g_wh+(long)(4+z)*WE+(long)n0*512; Bl=g_wl+(long)(4+z)*WE+(long)n0*512;
    }
    float acc[4][4][4];
    #pragma unroll
    for(int i=0;i<4;i++)
        #pragma unroll
        for(int j=0;j<4;j++)
            #pragma unroll
            for(int e=0;e<4;e++)acc[i][j][e]=0.f;

    auto issue=[&](int kc){
        uint32_t bs=sb+(uint32_t)(kc&1)*32768u;
        const __nv_bfloat16* a=Ah+kc*32; const __nv_bfloat16* a2=Al+kc*32;
        for(int c=tid;c<512;c+=256){int r=c>>2,q=c&3;
            uint32_t o=off64(r,q);
            cpa(bs+o,a+(long)r*512+q*8);
            cpa(bs+8192+o,a2+(long)r*512+q*8);}
        const __nv_bfloat16* b=Bh+kc*32; const __nv_bfloat16* b2=Bl+kc*32;
        for(int c=tid;c<512;c+=256){int r=c>>2,q=c&3;
            uint32_t o=off64(r,q);
            cpa(bs+16384+o,b+(long)r*512+q*8);
            cpa(bs+24576+o,b2+(long)r*512+q*8);}
        asm volatile("cp.async.commit_group;");
    };

    issue(0);
    for(int kc=0;kc<NCH;++kc){
        if(kc+1<NCH){issue(kc+1); asm volatile("cp.async.wait_group 1;");}
        else asm volatile("cp.async.wait_group 0;");
        __syncthreads();
        uint32_t bs=sb+(uint32_t)(kc&1)*32768u;
        #pragma unroll
        for(int kk=0;kk<2;++kk){
            uint32_t fbh[4][2],fbl[4][2];
            #pragma unroll
            for(int ni=0;ni<4;++ni){
                uint32_t ba=bs+16384+off64(wn0+ni*8+(l&7),kk*2+((l>>3)&1));
                ldm2(fbh[ni],ba); ldm2(fbl[ni],ba+8192);
            }
            uint32_t fa[4][4];
            #pragma unroll
            for(int mi=0;mi<4;++mi)
                ldm4(fa[mi],bs+off64(wm0+mi*16+(l&15),kk*2+(l>>4)));
            #pragma unroll
            for(int mi=0;mi<4;++mi)
                #pragma unroll
                for(int ni=0;ni<4;++ni){
                    hmma(acc[mi][ni],fa[mi],fbh[ni]);
                    hmma(acc[mi][ni],fa[mi],fbl[ni]);
                }
            #pragma unroll
            for(int mi=0;mi<4;++mi)
                ldm4(fa[mi],bs+8192+off64(wm0+mi*16+(l&15),kk*2+(l>>4)));
            #pragma unroll
            for(int mi=0;mi<4;++mi)
                #pragma unroll
                for(int ni=0;ni<4;++ni)
                    hmma(acc[mi][ni],fa[mi],fbh[ni]);
        }
        __syncthreads();
    }

    int g=l>>2,t=l&3;
    if(MODE==0){
        float sc=(z==0)?0.125f:1.f;
        if(z<2){
            __nv_bfloat16* dh=z?g_ckh:g_qkh; __nv_bfloat16* dl=z?g_ckl:g_qkl;
            #pragma unroll
            for(int mi=0;mi<4;++mi)
                #pragma unroll
                for(int h2=0;h2<2;++h2){
                    int row=wm0+mi*16+g+h2*8;
                    long a=(long)(m0+row)*512+n0;
                    #pragma unroll
                    for(int ni=0;ni<4;++ni){
                        float v0=acc[mi][ni][h2*2]*sc, v1=acc[mi][ni][h2*2+1]*sc;
                        __nv_bfloat16 h0,lo0,h1,lo1; spl(v0,h0,lo0); spl(v1,h1,lo1);
                        int col=wn0+ni*8+2*t;
                        *(uint32_t*)(dh+a+col)=pk2(h0,h1);
                        *(uint32_t*)(dl+a+col)=pk2(lo0,lo1);
                    }
                }
        } else {
            __nv_bfloat16* dh=(z==2)?g_vth:g_cvh; __nv_bfloat16* dl=(z==2)?g_vtl:g_cvl;
            #pragma unroll
            for(int mi=0;mi<4;++mi)
                #pragma unroll
                for(int e=0;e<4;++e){
                    int row=m0+wm0+mi*16+g+(e>>1)*8;
                    int bb=row>>11, ii=row&2047;
                    #pragma unroll
                    for(int ni=0;ni<4;++ni){
                        int inner=n0+wn0+ni*8+2*t+(e&1);
                        long a=((long)((bb*8+(inner>>6))*64+(inner&63)))*N_+ii;
                        float v=acc[mi][ni][e];
                        __nv_bfloat16 h,lo;spl(v,h,lo);
                        dh[a]=h; dl[a]=lo;
                    }
                }
        }
    } else {
        const float* bias=z?bi1:bi0;
        #pragma unroll
        for(int mi=0;mi<4;++mi)
            #pragma unroll
            for(int h2=0;h2<2;++h2){
                int row=wm0+mi*16+g+h2*8;
                float* dst=outp+((long)z*MR+m0+row)*512+n0;
                #pragma unroll
                for(int ni=0;ni<4;++ni){
                    int col=wn0+ni*8+2*t;
                    float2 v;
                    v.x=acc[mi][ni][h2*2]+bias[n0+col];
                    v.y=acc[mi][ni][h2*2+1]+bias[n0+col+1];
                    *(float2*)(dst+col)=v;
                }
            }
    }
}

// ---------------- symmetric flash attention (one direction per launch) ------
// All tiles 128B rows with SW128 swizzle.
constexpr int FQ=0;        // hi 16384, lo +16384
constexpr int FK=32768;    // hi 8192,  lo +8192
constexpr int FV=49152;    // hi 8192,  lo +8192
constexpr int FE=65536;    // hi 16384, lo +16384
constexpr int FR=98304;    // float[128]
constexpr int SMF2=98816;

__global__ void __launch_bounds__(256,2) fused2(
    const __nv_bfloat16* __restrict__ Qh,const __nv_bfloat16* __restrict__ Ql,
    const __nv_bfloat16* __restrict__ Kh,const __nv_bfloat16* __restrict__ Kl,
    const __nv_bfloat16* __restrict__ Vh,const __nv_bfloat16* __restrict__ Vl,
    __nv_bfloat16* __restrict__ Oh,__nv_bfloat16* __restrict__ Ol)
{
    extern __shared__ __align__(16) char sm[];
    uint32_t sb=s2u(sm);
    int tid=threadIdx.x,w=tid>>5,l=tid&31;
    int it=blockIdx.x, z=blockIdx.y, bq=z>>3, hq=z&7;
    int i0=it*128;
    long qoff=((long)(bq*2048+i0))*512+hq*64;
    long kbase=((long)(bq*2048))*512+hq*64;
    long vbase=(long)z*64*2048;
    float* srow=(float*)(sm+FR);
    if(tid<128) srow[tid]=0.f;

    for(int c=tid;c<1024;c+=256){int r=c>>3,q=c&7;
        uint32_t o=swz((uint32_t)(r*128+q*16));
        cpa(sb+FQ+o,       Qh+qoff+(long)r*512+q*8);
        cpa(sb+FQ+16384+o, Ql+qoff+(long)r*512+q*8);}
    auto issue_k=[&](int jc){
        for(int c=tid;c<512;c+=256){int r=c>>3,q=c&7;
            uint32_t o=swz((uint32_t)(r*128+q*16));
            cpa(sb+FK+o,      Kh+kbase+(long)(jc*64+r)*512+q*8);
            cpa(sb+FK+8192+o, Kl+kbase+(long)(jc*64+r)*512+q*8);}
        asm volatile("cp.async.commit_group;");
    };
    auto issue_v=[&](int jc){
        for(int c=tid;c<512;c+=256){int r=c>>3,q=c&7;
            uint32_t o=swz((uint32_t)(r*128+q*16));
            cpa(sb+FV+o,      Vh+vbase+(long)r*2048+jc*64+q*8);
            cpa(sb+FV+8192+o, Vl+vbase+(long)r*2048+jc*64+q*8);}
        asm volatile("cp.async.commit_group;");
    };
    issue_k(0); issue_v(0);

    int g=l>>2,t=l&3;
    int wm=(w>>1)*32, wn=(w&1)*32;
    float acc_o[2][4][4]; float rsum[2][2];
    #pragma unroll
    for(int i=0;i<2;i++)
        #pragma unroll
        for(int j=0;j<4;j++)
            #pragma unroll
            for(int e=0;e<4;e++)acc_o[i][j][e]=0.f;
    rsum[0][0]=rsum[0][1]=rsum[1][0]=rsum[1][1]=0.f;

    for(int jc=0;jc<32;++jc){
        asm volatile("cp.async.wait_group 1;");   // K(jc) (+Q at jc=0)
        __syncthreads();
        // ---- sim: Q(split) x K(split), 3 products, K=64 ----
        float s[2][4][4];
        #pragma unroll
        for(int i=0;i<2;i++)
            #pragma unroll
            for(int j=0;j<4;j++)
                #pragma unroll
                for(int e=0;e<4;e++)s[i][j][e]=0.f;
        #pragma unroll
        for(int kk=0;kk<4;++kk){
            uint32_t fbh[4][2],fbl[4][2];
            #pragma unroll
            for(int ni=0;ni<4;++ni){
                uint32_t ba=sb+FK+swz((uint32_t)((wn+ni*8+(l&7))*128+(kk*2+((l>>3)&1))*16));
                ldm2(fbh[ni],ba); ldm2(fbl[ni],ba+8192);
            }
            uint32_t fa[2][4];
            #pragma unroll
            for(int mi=0;mi<2;++mi)
                ldm4(fa[mi],sb+FQ+swz((uint32_t)((wm+mi*16+(l&15))*128+(kk*2+(l>>4))*16)));
            #pragma unroll
            for(int mi=0;mi<2;++mi)
                #pragma unroll
                for(int ni=0;ni<4;++ni){
                    hmma(s[mi][ni],fa[mi],fbh[ni]);
                    hmma(s[mi][ni],fa[mi],fbl[ni]);
                }
            #pragma unroll
            for(int mi=0;mi<2;++mi)
                ldm4(fa[mi],sb+FQ+16384+swz((uint32_t)((wm+mi*16+(l&15))*128+(kk*2+(l>>4))*16)));
            #pragma unroll
            for(int mi=0;mi<2;++mi)
                #pragma unroll
                for(int ni=0;ni<4;++ni)
                    hmma(s[mi][ni],fa[mi],fbh[ni]);
        }
        // ---- exp -> E smem (hi+lo), rowsum in regs ----
        #pragma unroll
        for(int mi=0;mi<2;++mi)
            #pragma unroll
            for(int h2=0;h2<2;++h2){
                float rp=0.f;
                int row=wm+mi*16+g+h2*8;
                #pragma unroll
                for(int ni=0;ni<4;++ni){
                    float e0=fexp(s[mi][ni][h2*2]), e1=fexp(s[mi][ni][h2*2+1]);
                    rp+=e0+e1;
                    __nv_bfloat16 h0,lo0,h1,lo1; spl(e0,h0,lo0); spl(e1,h1,lo1);
                    uint32_t cb=swz((uint32_t)(row*128+(wn+ni*8+2*t)*2));
                    *(uint32_t*)(sm+FE+cb)=pk2(h0,h1);
                    *(uint32_t*)(sm+FE+16384+cb)=pk2(lo0,lo1);
                }
                rp+=__shfl_xor_sync(0xffffffffu,rp,1);
                rp+=__shfl_xor_sync(0xffffffffu,rp,2);
                rsum[mi][h2]+=rp;
            }
        __syncthreads();                           // E ready; K consumed
        if(jc+1<32){ issue_k(jc+1); asm volatile("cp.async.wait_group 1;"); }
        else asm volatile("cp.async.wait_group 0;");
        __syncthreads();                           // V(jc) visible
        // ---- out: acc_o += Eh@(Vh+Vl) + El@Vh, K=64 ----
        #pragma unroll
        for(int kk=0;kk<4;++kk){
            uint32_t gbh[4][2],gbl[4][2];
            #pragma unroll
            for(int ni=0;ni<4;++ni){
                uint32_t ba=sb+FV+swz((uint32_t)((wn+ni*8+(l&7))*128+(kk*2+((l>>3)&1))*16));
                ldm2(gbh[ni],ba); ldm2(gbl[ni],ba+8192);
            }
            uint32_t fe[2][4];
            #pragma unroll
            for(int mi=0;mi<2;++mi)
                ldm4(fe[mi],sb+FE+swz((uint32_t)((wm+mi*16+(l&15))*128+(kk*2+(l>>4))*16)));
            #pragma unroll
            for(int mi=0;mi<2;++mi)
                #pragma unroll
                for(int ni=0;ni<4;++ni){
                    hmma(acc_o[mi][ni],fe[mi],gbh[ni]);
                    hmma(acc_o[mi][ni],fe[mi],gbl[ni]);
                }
            #pragma unroll
            for(int mi=0;mi<2;++mi)
                ldm4(fe[mi],sb+FE+16384+swz((uint32_t)((wm+mi*16+(l&15))*128+(kk*2+(l>>4))*16)));
            #pragma unroll
            for(int mi=0;mi<2;++mi)
                #pragma unroll
                for(int ni=0;ni<4;++ni)
                    hmma(acc_o[mi][ni],fe[mi],gbh[ni]);
        }
        __syncthreads();                           // V,E consumed
        if(jc+1<32) issue_v(jc+1);
    }
    // ---- rowsum combine, normalize, split-write ----
    #pragma unroll
    for(int mi=0;mi<2;++mi)
        #pragma unroll
        for(int h2=0;h2<2;++h2)
            if(t==0) atomicAdd(srow+wm+mi*16+g+h2*8,rsum[mi][h2]);
    __syncthreads();
    #pragma unroll
    for(int mi=0;mi<2;++mi)
        #pragma unroll
        for(int h2=0;h2<2;++h2){
            int row=wm+mi*16+g+h2*8;
            float inv=1.f/srow[row];
            long a=((long)(bq*2048+i0+row))*512+hq*64+wn;
            #pragma unroll
            for(int ni=0;ni<4;++ni){
                float v0=acc_o[mi][ni][h2*2]*inv, v1=acc_o[mi][ni][h2*2+1]*inv;
                __nv_bfloat16 h0,lo0,h1,lo1; spl(v0,h0,lo0); spl(v1,h1,lo1);
                *(uint32_t*)(Oh+a+ni*8+2*t)=pk2(h0,h1);
                *(uint32_t*)(Ol+a+ni*8+2*t)=pk2(lo0,lo1);
            }
        }
}

constexpr int SMBIG=65536;

extern "C" void kernel_launch(void* const* d_in,const int* in_sizes,int n_in,void* d_out,int out_size){
    (void)in_sizes;(void)n_in;(void)out_size;
    const float* x   =(const float*)d_in[0];
    const float* ctx =(const float*)d_in[1];
    const float* gx  =(const float*)d_in[2];
    const float* bx  =(const float*)d_in[3];
    const float* gc  =(const float*)d_in[4];
    const float* bc  =(const float*)d_in[5];
    const float* Wqk =(const float*)d_in[6];
    const float* Wcqk=(const float*)d_in[7];
    const float* Wv  =(const float*)d_in[8];
    const float* Wcv =(const float*)d_in[9];
    const float* Wout=(const float*)d_in[10];
    const float* bout=(const float*)d_in[11];
    const float* Wco =(const float*)d_in[12];
    const float* bco =(const float*)d_in[13];
    float* out=(float*)d_out;

    __nv_bfloat16 *qkh,*qkl,*ckh,*ckl,*vth,*vtl,*cvh,*cvl,*oh,*ol,*gh,*gl;
    cudaGetSymbolAddress((void**)&qkh,g_qkh); cudaGetSymbolAddress((void**)&qkl,g_qkl);
    cudaGetSymbolAddress((void**)&ckh,g_ckh); cudaGetSymbolAddress((void**)&ckl,g_ckl);
    cudaGetSymbolAddress((void**)&vth,g_vth); cudaGetSymbolAddress((void**)&vtl,g_vtl);
    cudaGetSymbolAddress((void**)&cvh,g_cvh); cudaGetSymbolAddress((void**)&cvl,g_cvl);
    cudaGetSymbolAddress((void**)&oh,g_oh);   cudaGetSymbolAddress((void**)&ol,g_ol);
    cudaGetSymbolAddress((void**)&gh,g_gh);   cudaGetSymbolAddress((void**)&gl,g_gl);

    cudaFuncSetAttribute(mm_k<0>,cudaFuncAttributeMaxDynamicSharedMemorySize,SMBIG);
    cudaFuncSetAttribute(mm_k<4>,cudaFuncAttributeMaxDynamicSharedMemorySize,SMBIG);
    cudaFuncSetAttribute(fused2,cudaFuncAttributeMaxDynamicSharedMemorySize,SMF2);

    ln_k<<<MR,128>>>(x,gx,bx,0);
    ln_k<<<MR,128>>>(ctx,gc,bc,1);
    wsplit_k<<<dim3(16,16,6),dim3(32,32)>>>(Wqk,Wcqk,Wv,Wcv,Wout,Wco);
    mm_k<0><<<dim3(4,32,4),256,SMBIG>>>(nullptr,nullptr,nullptr);
    fused2<<<dim3(16,16),256,SMF2>>>(qkh,qkl,ckh,ckl,cvh,cvl,oh,ol);   // x side
    fused2<<<dim3(16,16),256,SMF2>>>(ckh,ckl,qkh,qkl,vth,vtl,gh,gl);   // ctx side
    mm_k<4><<<dim3(4,32,2),256,SMBIG>>>(out,bout,bco);
}

// round 11
// speedup vs baseline: 1.0859x; 1.0009x over previous
#include <cuda_runtime.h>
#include <cuda_bf16.h>
#include <cstdint>

#define DI __device__ __forceinline__
constexpr int N_=2048, D_=512, MR=4096, WE=262144;

__device__ __nv_bfloat16 g_xnh[MR*D_],g_xnl[MR*D_],g_cnh[MR*D_],g_cnl[MR*D_];
__device__ __nv_bfloat16 g_qkh[MR*D_],g_qkl[MR*D_],g_ckh[MR*D_],g_ckl[MR*D_];
__device__ __nv_bfloat16 g_vth[MR*D_],g_vtl[MR*D_],g_cvh[MR*D_],g_cvl[MR*D_];
__device__ __nv_bfloat16 g_oh[MR*D_],g_ol[MR*D_],g_gh[MR*D_],g_gl[MR*D_];
__device__ __nv_bfloat16 g_wh[6*WE],g_wl[6*WE];

DI uint32_t s2u(const void* p){uint32_t a;asm("{ .reg .u64 t; cvta.to.shared.u64 t,%1; cvt.u32.u64 %0,t; }":"=r"(a):"l"(p));return a;}
DI void ldm4(uint32_t* r,uint32_t a){
    asm volatile("ldmatrix.sync.aligned.m8n8.x4.shared.b16 {%0,%1,%2,%3},[%4];"
        :"=r"(r[0]),"=r"(r[1]),"=r"(r[2]),"=r"(r[3]):"r"(a));
}
DI void hmma(float* c,const uint32_t* a,const uint32_t* b){
    asm volatile("mma.sync.aligned.m16n8k16.row.col.f32.bf16.bf16.f32 {%0,%1,%2,%3},{%4,%5,%6,%7},{%8,%9},{%0,%1,%2,%3};"
        :"+f"(c[0]),"+f"(c[1]),"+f"(c[2]),"+f"(c[3])
        :"r"(a[0]),"r"(a[1]),"r"(a[2]),"r"(a[3]),"r"(b[0]),"r"(b[1]));
}
DI void cpa(uint32_t d,const void* s){asm volatile("cp.async.cg.shared.global [%0],[%1],16;"::"r"(d),"l"(s));}

// 64B-row 2-bit swizzle (4 chunks of 16B per row)
DI uint32_t off64(int r,int q){return (uint32_t)(r*64+((q^((r>>1)&3))<<4));}
// 128B-row SW128 swizzle
DI uint32_t swz(uint32_t o){return o^((o>>3)&0x70);}

DI float fexp(float x){
    x=fmaxf(x,-80.f); float t=x*1.4426950408889634f;
    float z=t+12582912.f, fi=z-12582912.f, f=t-fi;
    int i=__float_as_int(z)-0x4B400000;
    float p=1.3333558146428443e-3f;
    p=fmaf(p,f,9.618129107628477e-3f); p=fmaf(p,f,5.550410866482158e-2f);
    p=fmaf(p,f,2.402265069591007e-1f); p=fmaf(p,f,6.931471805599453e-1f);
    p=fmaf(p,f,1.0f);
    return __int_as_float(__float_as_int(p)+(i<<23));
}
DI void spl(float v,__nv_bfloat16&h,__nv_bfloat16&l){h=__float2bfloat16(v);l=__float2bfloat16(v-__bfloat162float(h));}
DI uint32_t pk2(__nv_bfloat16 a,__nv_bfloat16 b){return ((uint32_t)__bfloat16_as_ushort(b)<<16)|(uint32_t)__bfloat16_as_ushort(a);}

DI float wred(float v){
    #pragma unroll
    for(int o=16;o>0;o>>=1)v+=__shfl_xor_sync(0xffffffffu,v,o);
    return v;
}
__global__ void ln_k(const float* __restrict__ x,const float* __restrict__ g,const float* __restrict__ b,int which){
    __shared__ float sh[8];
    long row=blockIdx.x;
    float4 v=((const float4*)(x+row*D_))[threadIdx.x];
    float s=v.x+v.y+v.z+v.w, sq=v.x*v.x+v.y*v.y+v.z*v.z+v.w*v.w;
    int l=threadIdx.x&31,w=threadIdx.x>>5;
    s=wred(s);sq=wred(sq);
    if(l==0){sh[w]=s;sh[4+w]=sq;}
    __syncthreads();
    s=sh[0]+sh[1]+sh[2]+sh[3]; sq=sh[4]+sh[5]+sh[6]+sh[7];
    float mu=s/D_, rstd=rsqrtf(sq/D_-mu*mu+1e-5f);
    float4 gg=((const float4*)g)[threadIdx.x], bb=((const float4*)b)[threadIdx.x];
    float o0=(v.x-mu)*rstd*gg.x+bb.x, o1=(v.y-mu)*rstd*gg.y+bb.y;
    float o2=(v.z-mu)*rstd*gg.z+bb.z, o3=(v.w-mu)*rstd*gg.w+bb.w;
    __nv_bfloat16 h0,h1,h2,h3,l0,l1,l2,l3;
    spl(o0,h0,l0);spl(o1,h1,l1);spl(o2,h2,l2);spl(o3,h3,l3);
    __nv_bfloat16* dh=which?g_cnh:g_xnh; __nv_bfloat16* dl=which?g_cnl:g_xnl;
    long a=row*D_+threadIdx.x*4;
    *(uint2*)(dh+a)=make_uint2(pk2(h0,h1),pk2(h2,h3));
    *(uint2*)(dl+a)=make_uint2(pk2(l0,l1),pk2(l2,l3));
}
__global__ void wsplit_k(const float* w0,const float* w1,const float* w2,const float* w3,const float* w4,const float* w5){
    __shared__ float t[32][33];
    int z=blockIdx.z;
    const float* W=(z==0)?w0:(z==1)?w1:(z==2)?w2:(z==3)?w3:(z==4)?w4:w5;
    int n0=blockIdx.x*32,k0=blockIdx.y*32,tx=threadIdx.x,ty=threadIdx.y;
    t[ty][tx]=W[(long)(k0+ty)*512+n0+tx];
    __syncthreads();
    float v=t[tx][ty];
    long a=(long)z*WE+(long)(n0+ty)*512+k0+tx;
    __nv_bfloat16 h,l;spl(v,h,l); g_wh[a]=h;g_wl[a]=l;
}

// MODE 0: input projections (z: 0 qk,1 cqk,2 v,3 cv)   MODE 4: final proj
// smem per stage: Ah 8K | Al 8K | Bh 8K | Bl 8K = 32K; double-buffered = 64K
template<int MODE>
__global__ void __launch_bounds__(256,2) mm_k(float* outp,const float* bi0,const float* bi1){
    extern __shared__ __align__(16) char sm[];
    constexpr int NCH=16;
    uint32_t sb=s2u(sm);
    int tid=threadIdx.x,w=tid>>5,l=tid&31,z=blockIdx.z;
    int m0=blockIdx.y*128, n0=blockIdx.x*128;
    int wm0=(w>>2)*64, wn0=(w&3)*32;

    const __nv_bfloat16 *Ah,*Al,*Bh,*Bl;
    if(MODE==0){
        Ah=((z&1)?g_cnh:g_xnh)+(long)m0*512; Al=((z&1)?g_cnl:g_xnl)+(long)m0*512;
        Bh=g_wh+(long)z*WE+(long)n0*512; Bl=g_wl+(long)z*WE+(long)n0*512;
    } else {
        Ah=(z?g_gh:g_oh)+(long)m0*512; Al=(z?g_gl:g_ol)+(long)m0*512;
        Bh=g_wh+(long)(4+z)*WE+(long)n0*512; Bl=g_wl+(long)(4+z)*WE+(long)n0*512;
    }
    float acc[4][4][4];
    #pragma unroll
    for(int i=0;i<4;i++)
        #pragma unroll
        for(int j=0;j<4;j++)
            #pragma unroll
            for(int e=0;e<4;e++)acc[i][j][e]=0.f;

    auto issue=[&](int kc){
        uint32_t bs=sb+(uint32_t)(kc&1)*32768u;
        const __nv_bfloat16* a=Ah+kc*32; const __nv_bfloat16* a2=Al+kc*32;
        for(int c=tid;c<512;c+=256){int r=c>>2,q=c&3;
            uint32_t o=off64(r,q);
            cpa(bs+o,a+(long)r*512+q*8);
            cpa(bs+8192+o,a2+(long)r*512+q*8);}
        const __nv_bfloat16* b=Bh+kc*32; const __nv_bfloat16* b2=Bl+kc*32;
        for(int c=tid;c<512;c+=256){int r=c>>2,q=c&3;
            uint32_t o=off64(r,q);
            cpa(bs+16384+o,b+(long)r*512+q*8);
            cpa(bs+24576+o,b2+(long)r*512+q*8);}
        asm volatile("cp.async.commit_group;");
    };

    issue(0);
    for(int kc=0;kc<NCH;++kc){
        if(kc+1<NCH){issue(kc+1); asm volatile("cp.async.wait_group 1;");}
        else asm volatile("cp.async.wait_group 0;");
        __syncthreads();
        uint32_t bs=sb+(uint32_t)(kc&1)*32768u;
        int gr8=((l>>4)&1)*8, kch=(l>>3)&1;
        #pragma unroll
        for(int kk=0;kk<2;++kk){
            uint32_t fbh[4][2],fbl[4][2];
            #pragma unroll
            for(int p=0;p<2;++p){
                uint32_t ba=bs+16384+off64(wn0+p*16+gr8+(l&7),kk*2+kch);
                uint32_t r[4];
                ldm4(r,ba);
                fbh[2*p][0]=r[0];fbh[2*p][1]=r[1];fbh[2*p+1][0]=r[2];fbh[2*p+1][1]=r[3];
                ldm4(r,ba+8192);
                fbl[2*p][0]=r[0];fbl[2*p][1]=r[1];fbl[2*p+1][0]=r[2];fbl[2*p+1][1]=r[3];
            }
            uint32_t fa[4][4];
            #pragma unroll
            for(int mi=0;mi<4;++mi)
                ldm4(fa[mi],bs+off64(wm0+mi*16+(l&15),kk*2+(l>>4)));
            #pragma unroll
            for(int mi=0;mi<4;++mi)
                #pragma unroll
                for(int ni=0;ni<4;++ni){
                    hmma(acc[mi][ni],fa[mi],fbh[ni]);
                    hmma(acc[mi][ni],fa[mi],fbl[ni]);
                }
            #pragma unroll
            for(int mi=0;mi<4;++mi)
                ldm4(fa[mi],bs+8192+off64(wm0+mi*16+(l&15),kk*2+(l>>4)));
            #pragma unroll
            for(int mi=0;mi<4;++mi)
                #pragma unroll
                for(int ni=0;ni<4;++ni)
                    hmma(acc[mi][ni],fa[mi],fbh[ni]);
        }
        __syncthreads();
    }

    int g=l>>2,t=l&3;
    if(MODE==0){
        float sc=(z==0)?0.125f:1.f;
        if(z<2){
            __nv_bfloat16* dh=z?g_ckh:g_qkh; __nv_bfloat16* dl=z?g_ckl:g_qkl;
            #pragma unroll
            for(int mi=0;mi<4;++mi)
                #pragma unroll
                for(int h2=0;h2<2;++h2){
                    int row=wm0+mi*16+g+h2*8;
                    long a=(long)(m0+row)*512+n0;
                    #pragma unroll
                    for(int ni=0;ni<4;++ni){
                        float v0=acc[mi][ni][h2*2]*sc, v1=acc[mi][ni][h2*2+1]*sc;
                        __nv_bfloat16 h0,lo0,h1,lo1; spl(v0,h0,lo0); spl(v1,h1,lo1);
                        int col=wn0+ni*8+2*t;
                        *(uint32_t*)(dh+a+col)=pk2(h0,h1);
                        *(uint32_t*)(dl+a+col)=pk2(lo0,lo1);
                    }
                }
        } else {
            __nv_bfloat16* dh=(z==2)?g_vth:g_cvh; __nv_bfloat16* dl=(z==2)?g_vtl:g_cvl;
            #pragma unroll
            for(int mi=0;mi<4;++mi)
                #pragma unroll
                for(int e=0;e<4;++e){
                    int row=m0+wm0+mi*16+g+(e>>1)*8;
                    int bb=row>>11, ii=row&2047;
                    #pragma unroll
                    for(int ni=0;ni<4;++ni){
                        int inner=n0+wn0+ni*8+2*t+(e&1);
                        long a=((long)((bb*8+(inner>>6))*64+(inner&63)))*N_+ii;
                        float v=acc[mi][ni][e];
                        __nv_bfloat16 h,lo;spl(v,h,lo);
                        dh[a]=h; dl[a]=lo;
                    }
                }
        }
    } else {
        const float* bias=z?bi1:bi0;
        #pragma unroll
        for(int mi=0;mi<4;++mi)
            #pragma unroll
            for(int h2=0;h2<2;++h2){
                int row=wm0+mi*16+g+h2*8;
                float* dst=outp+((long)z*MR+m0+row)*512+n0;
                #pragma unroll
                for(int ni=0;ni<4;++ni){
                    int col=wn0+ni*8+2*t;
                    float2 v;
                    v.x=acc[mi][ni][h2*2]+bias[n0+col];
                    v.y=acc[mi][ni][h2*2+1]+bias[n0+col+1];
                    *(float2*)(dst+col)=v;
                }
            }
    }
}

// ---------------- symmetric flash attention (one direction per launch) ------
// All tiles 128B rows with SW128 swizzle.
constexpr int FQ=0;        // hi 16384, lo +16384
constexpr int FK=32768;    // hi 8192,  lo +8192
constexpr int FV=49152;    // hi 8192,  lo +8192
constexpr int FE=65536;    // hi 16384, lo +16384
constexpr int FR=98304;    // float[128]
constexpr int SMF2=98816;

__global__ void __launch_bounds__(256,2) fused2(
    const __nv_bfloat16* __restrict__ Qh,const __nv_bfloat16* __restrict__ Ql,
    const __nv_bfloat16* __restrict__ Kh,const __nv_bfloat16* __restrict__ Kl,
    const __nv_bfloat16* __restrict__ Vh,const __nv_bfloat16* __restrict__ Vl,
    __nv_bfloat16* __restrict__ Oh,__nv_bfloat16* __restrict__ Ol)
{
    extern __shared__ __align__(16) char sm[];
    uint32_t sb=s2u(sm);
    int tid=threadIdx.x,w=tid>>5,l=tid&31;
    int it=blockIdx.x, z=blockIdx.y, bq=z>>3, hq=z&7;
    int i0=it*128;
    long qoff=((long)(bq*2048+i0))*512+hq*64;
    long kbase=((long)(bq*2048))*512+hq*64;
    long vbase=(long)z*64*2048;
    float* srow=(float*)(sm+FR);
    if(tid<128) srow[tid]=0.f;

    for(int c=tid;c<1024;c+=256){int r=c>>3,q=c&7;
        uint32_t o=swz((uint32_t)(r*128+q*16));
        cpa(sb+FQ+o,       Qh+qoff+(long)r*512+q*8);
        cpa(sb+FQ+16384+o, Ql+qoff+(long)r*512+q*8);}
    auto issue_k=[&](int jc){
        for(int c=tid;c<512;c+=256){int r=c>>3,q=c&7;
            uint32_t o=swz((uint32_t)(r*128+q*16));
            cpa(sb+FK+o,      Kh+kbase+(long)(jc*64+r)*512+q*8);
            cpa(sb+FK+8192+o, Kl+kbase+(long)(jc*64+r)*512+q*8);}
        asm volatile("cp.async.commit_group;");
    };
    auto issue_v=[&](int jc){
        for(int c=tid;c<512;c+=256){int r=c>>3,q=c&7;
            uint32_t o=swz((uint32_t)(r*128+q*16));
            cpa(sb+FV+o,      Vh+vbase+(long)r*2048+jc*64+q*8);
            cpa(sb+FV+8192+o, Vl+vbase+(long)r*2048+jc*64+q*8);}
        asm volatile("cp.async.commit_group;");
    };
    issue_k(0); issue_v(0);

    int g=l>>2,t=l&3;
    int wm=(w>>1)*32, wn=(w&1)*32;
    int gr8=((l>>4)&1)*8, kch=(l>>3)&1;
    float acc_o[2][4][4]; float rsum[2][2];
    #pragma unroll
    for(int i=0;i<2;i++)
        #pragma unroll
        for(int j=0;j<4;j++)
            #pragma unroll
            for(int e=0;e<4;e++)acc_o[i][j][e]=0.f;
    rsum[0][0]=rsum[0][1]=rsum[1][0]=rsum[1][1]=0.f;

    for(int jc=0;jc<32;++jc){
        asm volatile("cp.async.wait_group 1;");   // K(jc) (+Q at jc=0)
        __syncthreads();
        // ---- sim: Q(split) x K(split), 3 products, K=64 ----
        float s[2][4][4];
        #pragma unroll
        for(int i=0;i<2;i++)
            #pragma unroll
            for(int j=0;j<4;j++)
                #pragma unroll
                for(int e=0;e<4;e++)s[i][j][e]=0.f;
        #pragma unroll
        for(int kk=0;kk<4;++kk){
            uint32_t fbh[4][2],fbl[4][2];
            #pragma unroll
            for(int p=0;p<2;++p){
                uint32_t ba=sb+FK+swz((uint32_t)((wn+p*16+gr8+(l&7))*128+(kk*2+kch)*16));
                uint32_t r[4];
                ldm4(r,ba);
                fbh[2*p][0]=r[0];fbh[2*p][1]=r[1];fbh[2*p+1][0]=r[2];fbh[2*p+1][1]=r[3];
                ldm4(r,ba+8192);
                fbl[2*p][0]=r[0];fbl[2*p][1]=r[1];fbl[2*p+1][0]=r[2];fbl[2*p+1][1]=r[3];
            }
            uint32_t fa[2][4];
            #pragma unroll
            for(int mi=0;mi<2;++mi)
                ldm4(fa[mi],sb+FQ+swz((uint32_t)((wm+mi*16+(l&15))*128+(kk*2+(l>>4))*16)));
            #pragma unroll
            for(int mi=0;mi<2;++mi)
                #pragma unroll
                for(int ni=0;ni<4;++ni){
                    hmma(s[mi][ni],fa[mi],fbh[ni]);
                    hmma(s[mi][ni],fa[mi],fbl[ni]);
                }
            #pragma unroll
            for(int mi=0;mi<2;++mi)
                ldm4(fa[mi],sb+FQ+16384+swz((uint32_t)((wm+mi*16+(l&15))*128+(kk*2+(l>>4))*16)));
            #pragma unroll
            for(int mi=0;mi<2;++mi)
                #pragma unroll
                for(int ni=0;ni<4;++ni)
                    hmma(s[mi][ni],fa[mi],fbh[ni]);
        }
        // ---- exp -> E smem (hi+lo), rowsum in regs ----
        #pragma unroll
        for(int mi=0;mi<2;++mi)
            #pragma unroll
            for(int h2=0;h2<2;++h2){
                float rp=0.f;
                int row=wm+mi*16+g+h2*8;
                #pragma unroll
                for(int ni=0;ni<4;++ni){
                    float e0=fexp(s[mi][ni][h2*2]), e1=fexp(s[mi][ni][h2*2+1]);
                    rp+=e0+e1;
                    __nv_bfloat16 h0,lo0,h1,lo1; spl(e0,h0,lo0); spl(e1,h1,lo1);
                    uint32_t cb=swz((uint32_t)(row*128+(wn+ni*8+2*t)*2));
                    *(uint32_t*)(sm+FE+cb)=pk2(h0,h1);
                    *(uint32_t*)(sm+FE+16384+cb)=pk2(lo0,lo1);
                }
                rp+=__shfl_xor_sync(0xffffffffu,rp,1);
                rp+=__shfl_xor_sync(0xffffffffu,rp,2);
                rsum[mi][h2]+=rp;
            }
        __syncthreads();                           // E ready; K consumed
        if(jc+1<32){ issue_k(jc+1); asm volatile("cp.async.wait_group 1;"); }
        else asm volatile("cp.async.wait_group 0;");
        __syncthreads();                           // V(jc) visible
        // ---- out: acc_o += Eh@(Vh+Vl) + El@Vh, K=64 ----
        #pragma unroll
        for(int kk=0;kk<4;++kk){
            uint32_t gbh[4][2],gbl[4][2];
            #pragma unroll
            for(int p=0;p<2;++p){
                uint32_t ba=sb+FV+swz((uint32_t)((wn+p*16+gr8+(l&7))*128+(kk*2+kch)*16));
                uint32_t r[4];
                ldm4(r,ba);
                gbh[2*p][0]=r[0];gbh[2*p][1]=r[1];gbh[2*p+1][0]=r[2];gbh[2*p+1][1]=r[3];
                ldm4(r,ba+8192);
                gbl[2*p][0]=r[0];gbl[2*p][1]=r[1];gbl[2*p+1][0]=r[2];gbl[2*p+1][1]=r[3];
            }
            uint32_t fe[2][4];
            #pragma unroll
            for(int mi=0;mi<2;++mi)
                ldm4(fe[mi],sb+FE+swz((uint32_t)((wm+mi*16+(l&15))*128+(kk*2+(l>>4))*16)));
            #pragma unroll
            for(int mi=0;mi<2;++mi)
                #pragma unroll
                for(int ni=0;ni<4;++ni){
                    hmma(acc_o[mi][ni],fe[mi],gbh[ni]);
                    hmma(acc_o[mi][ni],fe[mi],gbl[ni]);
                }
            #pragma unroll
            for(int mi=0;mi<2;++mi)
                ldm4(fe[mi],sb+FE+16384+swz((uint32_t)((wm+mi*16+(l&15))*128+(kk*2+(l>>4))*16)));
            #pragma unroll
            for(int mi=0;mi<2;++mi)
                #pragma unroll
                for(int ni=0;ni<4;++ni)
                    hmma(acc_o[mi][ni],fe[mi],gbh[ni]);
        }
        __syncthreads();                           // V,E consumed
        if(jc+1<32) issue_v(jc+1);
    }
    // ---- rowsum combine, normalize, split-write ----
    #pragma unroll
    for(int mi=0;mi<2;++mi)
        #pragma unroll
        for(int h2=0;h2<2;++h2)
            if(t==0) atomicAdd(srow+wm+mi*16+g+h2*8,rsum[mi][h2]);
    __syncthreads();
    #pragma unroll
    for(int mi=0;mi<2;++mi)
        #pragma unroll
        for(int h2=0;h2<2;++h2){
            int row=wm+mi*16+g+h2*8;
            float inv=1.f/srow[row];
            long a=((long)(bq*2048+i0+row))*512+hq*64+wn;
            #pragma unroll
            for(int ni=0;ni<4;++ni){
                float v0=acc_o[mi][ni][h2*2]*inv, v1=acc_o[mi][ni][h2*2+1]*inv;
                __nv_bfloat16 h0,lo0,h1,lo1; spl(v0,h0,lo0); spl(v1,h1,lo1);
                *(uint32_t*)(Oh+a+ni*8+2*t)=pk2(h0,h1);
                *(uint32_t*)(Ol+a+ni*8+2*t)=pk2(lo0,lo1);
            }
        }
}

constexpr int SMBIG=65536;

extern "C" void kernel_launch(void* const* d_in,const int* in_sizes,int n_in,void* d_out,int out_size){
    (void)in_sizes;(void)n_in;(void)out_size;
    const float* x   =(const float*)d_in[0];
    const float* ctx =(const float*)d_in[1];
    const float* gx  =(const float*)d_in[2];
    const float* bx  =(const float*)d_in[3];
    const float* gc  =(const float*)d_in[4];
    const float* bc  =(const float*)d_in[5];
    const float* Wqk =(const float*)d_in[6];
    const float* Wcqk=(const float*)d_in[7];
    const float* Wv  =(const float*)d_in[8];
    const float* Wcv =(const float*)d_in[9];
    const float* Wout=(const float*)d_in[10];
    const float* bout=(const float*)d_in[11];
    const float* Wco =(const float*)d_in[12];
    const float* bco =(const float*)d_in[13];
    float* out=(float*)d_out;

    __nv_bfloat16 *qkh,*qkl,*ckh,*ckl,*vth,*vtl,*cvh,*cvl,*oh,*ol,*gh,*gl;
    cudaGetSymbolAddress((void**)&qkh,g_qkh); cudaGetSymbolAddress((void**)&qkl,g_qkl);
    cudaGetSymbolAddress((void**)&ckh,g_ckh); cudaGetSymbolAddress((void**)&ckl,g_ckl);
    cudaGetSymbolAddress((void**)&vth,g_vth); cudaGetSymbolAddress((void**)&vtl,g_vtl);
    cudaGetSymbolAddress((void**)&cvh,g_cvh); cudaGetSymbolAddress((void**)&cvl,g_cvl);
    cudaGetSymbolAddress((void**)&oh,g_oh);   cudaGetSymbolAddress((void**)&ol,g_ol);
    cudaGetSymbolAddress((void**)&gh,g_gh);   cudaGetSymbolAddress((void**)&gl,g_gl);

    cudaFuncSetAttribute(mm_k<0>,cudaFuncAttributeMaxDynamicSharedMemorySize,SMBIG);
    cudaFuncSetAttribute(mm_k<4>,cudaFuncAttributeMaxDynamicSharedMemorySize,SMBIG);
    cudaFuncSetAttribute(fused2,cudaFuncAttributeMaxDynamicSharedMemorySize,SMF2);

    ln_k<<<MR,128>>>(x,gx,bx,0);
    ln_k<<<MR,128>>>(ctx,gc,bc,1);
    wsplit_k<<<dim3(16,16,6),dim3(32,32)>>>(Wqk,Wcqk,Wv,Wcv,Wout,Wco);
    mm_k<0><<<dim3(4,32,4),256,SMBIG>>>(nullptr,nullptr,nullptr);
    fused2<<<dim3(16,16),256,SMF2>>>(qkh,qkl,ckh,ckl,cvh,cvl,oh,ol);   // x side
    fused2<<<dim3(16,16),256,SMF2>>>(ckh,ckl,qkh,qkl,vth,vtl,gh,gl);   // ctx side
    mm_k<4><<<dim3(4,32,2),256,SMBIG>>>(out,bout,bco);
}

// round 14
// speedup vs baseline: 1.1180x; 1.0295x over previous
#include <cuda_runtime.h>
#include <cuda_bf16.h>
#include <cstdint>

#define DI __device__ __forceinline__
constexpr int N_=2048, D_=512, MR=4096, WE=262144;

__device__ __nv_bfloat16 g_xnh[MR*D_],g_xnl[MR*D_],g_cnh[MR*D_],g_cnl[MR*D_];
__device__ __nv_bfloat16 g_qkh[MR*D_],g_qkl[MR*D_],g_ckh[MR*D_],g_ckl[MR*D_];
__device__ __nv_bfloat16 g_vth[MR*D_],g_vtl[MR*D_],g_cvh[MR*D_],g_cvl[MR*D_];
__device__ __nv_bfloat16 g_oh[MR*D_],g_ol[MR*D_],g_gh[MR*D_],g_gl[MR*D_];
__device__ __nv_bfloat16 g_wh[6*WE],g_wl[6*WE];

DI uint32_t s2u(const void* p){uint32_t a;asm("{ .reg .u64 t; cvta.to.shared.u64 t,%1; cvt.u32.u64 %0,t; }":"=r"(a):"l"(p));return a;}
DI void ldm4(uint32_t* r,uint32_t a){
    asm volatile("ldmatrix.sync.aligned.m8n8.x4.shared.b16 {%0,%1,%2,%3},[%4];"
        :"=r"(r[0]),"=r"(r[1]),"=r"(r[2]),"=r"(r[3]):"r"(a));
}
DI void hmma(float* c,const uint32_t* a,const uint32_t* b){
    asm volatile("mma.sync.aligned.m16n8k16.row.col.f32.bf16.bf16.f32 {%0,%1,%2,%3},{%4,%5,%6,%7},{%8,%9},{%0,%1,%2,%3};"
        :"+f"(c[0]),"+f"(c[1]),"+f"(c[2]),"+f"(c[3])
        :"r"(a[0]),"r"(a[1]),"r"(a[2]),"r"(a[3]),"r"(b[0]),"r"(b[1]));
}
DI void cpa(uint32_t d,const void* s){asm volatile("cp.async.cg.shared.global [%0],[%1],16;"::"r"(d),"l"(s));}

DI uint32_t off64(int r,int q){return (uint32_t)(r*64+((q^((r>>1)&3))<<4));}
DI uint32_t swz(uint32_t o){return o^((o>>3)&0x70);}

DI float fexp(float x){
    x=fmaxf(x,-80.f); float t=x*1.4426950408889634f;
    float z=t+12582912.f, fi=z-12582912.f, f=t-fi;
    int i=__float_as_int(z)-0x4B400000;
    float p=1.3333558146428443e-3f;
    p=fmaf(p,f,9.618129107628477e-3f); p=fmaf(p,f,5.550410866482158e-2f);
    p=fmaf(p,f,2.402265069591007e-1f); p=fmaf(p,f,6.931471805599453e-1f);
    p=fmaf(p,f,1.0f);
    return __int_as_float(__float_as_int(p)+(i<<23));
}
DI void spl(float v,__nv_bfloat16&h,__nv_bfloat16&l){h=__float2bfloat16(v);l=__float2bfloat16(v-__bfloat162float(h));}
DI uint32_t pk2(__nv_bfloat16 a,__nv_bfloat16 b){return ((uint32_t)__bfloat16_as_ushort(b)<<16)|(uint32_t)__bfloat16_as_ushort(a);}

DI float wred(float v){
    #pragma unroll
    for(int o=16;o>0;o>>=1)v+=__shfl_xor_sync(0xffffffffu,v,o);
    return v;
}
__global__ void ln_k(const float* __restrict__ x,const float* __restrict__ g,const float* __restrict__ b,int which){
    __shared__ float sh[8];
    long row=blockIdx.x;
    float4 v=((const float4*)(x+row*D_))[threadIdx.x];
    float s=v.x+v.y+v.z+v.w, sq=v.x*v.x+v.y*v.y+v.z*v.z+v.w*v.w;
    int l=threadIdx.x&31,w=threadIdx.x>>5;
    s=wred(s);sq=wred(sq);
    if(l==0){sh[w]=s;sh[4+w]=sq;}
    __syncthreads();
    s=sh[0]+sh[1]+sh[2]+sh[3]; sq=sh[4]+sh[5]+sh[6]+sh[7];
    float mu=s/D_, rstd=rsqrtf(sq/D_-mu*mu+1e-5f);
    float4 gg=((const float4*)g)[threadIdx.x], bb=((const float4*)b)[threadIdx.x];
    float o0=(v.x-mu)*rstd*gg.x+bb.x, o1=(v.y-mu)*rstd*gg.y+bb.y;
    float o2=(v.z-mu)*rstd*gg.z+bb.z, o3=(v.w-mu)*rstd*gg.w+bb.w;
    __nv_bfloat16 h0,h1,h2,h3,l0,l1,l2,l3;
    spl(o0,h0,l0);spl(o1,h1,l1);spl(o2,h2,l2);spl(o3,h3,l3);
    __nv_bfloat16* dh=which?g_cnh:g_xnh; __nv_bfloat16* dl=which?g_cnl:g_xnl;
    long a=row*D_+threadIdx.x*4;
    *(uint2*)(dh+a)=make_uint2(pk2(h0,h1),pk2(h2,h3));
    *(uint2*)(dl+a)=make_uint2(pk2(l0,l1),pk2(l2,l3));
}
__global__ void wsplit_k(const float* w0,const float* w1,const float* w2,const float* w3,const float* w4,const float* w5){
    __shared__ float t[32][33];
    int z=blockIdx.z;
    const float* W=(z==0)?w0:(z==1)?w1:(z==2)?w2:(z==3)?w3:(z==4)?w4:w5;
    int n0=blockIdx.x*32,k0=blockIdx.y*32,tx=threadIdx.x,ty=threadIdx.y;
    t[ty][tx]=W[(long)(k0+ty)*512+n0+tx];
    __syncthreads();
    float v=t[tx][ty];
    long a=(long)z*WE+(long)(n0+ty)*512+k0+tx;
    __nv_bfloat16 h,l;spl(v,h,l); g_wh[a]=h;g_wl[a]=l;
}

// MODE 0: input projections (z: 0 qk,1 cqk,2 v,3 cv)   MODE 4: final proj
template<int MODE>
__global__ void __launch_bounds__(256,2) mm_k(float* outp,const float* bi0,const float* bi1){
    extern __shared__ __align__(16) char sm[];
    constexpr int NCH=16;
    uint32_t sb=s2u(sm);
    int tid=threadIdx.x,w=tid>>5,l=tid&31,z=blockIdx.z;
    int m0=blockIdx.y*128, n0=blockIdx.x*128;
    int wm0=(w>>2)*64, wn0=(w&3)*32;

    const __nv_bfloat16 *Ah,*Al,*Bh,*Bl;
    if(MODE==0){
        Ah=((z&1)?g_cnh:g_xnh)+(long)m0*512; Al=((z&1)?g_cnl:g_xnl)+(long)m0*512;
        Bh=g_wh+(long)z*WE+(long)n0*512; Bl=g_wl+(long)z*WE+(long)n0*512;
    } else {
        Ah=(z?g_gh:g_oh)+(long)m0*512; Al=(z?g_gl:g_ol)+(long)m0*512;
        Bh=g_wh+(long)(4+z)*WE+(long)n0*512; Bl=g_wl+(long)(4+z)*WE+(long)n0*512;
    }
    float acc[4][4][4];
    #pragma unroll
    for(int i=0;i<4;i++)
        #pragma unroll
        for(int j=0;j<4;j++)
            #pragma unroll
            for(int e=0;e<4;e++)acc[i][j][e]=0.f;

    auto issue=[&](int kc){
        uint32_t bs=sb+(uint32_t)(kc&1)*32768u;
        const __nv_bfloat16* a=Ah+kc*32; const __nv_bfloat16* a2=Al+kc*32;
        for(int c=tid;c<512;c+=256){int r=c>>2,q=c&3;
            uint32_t o=off64(r,q);
            cpa(bs+o,a+(long)r*512+q*8);
            cpa(bs+8192+o,a2+(long)r*512+q*8);}
        const __nv_bfloat16* b=Bh+kc*32; const __nv_bfloat16* b2=Bl+kc*32;
        for(int c=tid;c<512;c+=256){int r=c>>2,q=c&3;
            uint32_t o=off64(r,q);
            cpa(bs+16384+o,b+(long)r*512+q*8);
            cpa(bs+24576+o,b2+(long)r*512+q*8);}
        asm volatile("cp.async.commit_group;");
    };

    issue(0);
    for(int kc=0;kc<NCH;++kc){
        if(kc+1<NCH){issue(kc+1); asm volatile("cp.async.wait_group 1;");}
        else asm volatile("cp.async.wait_group 0;");
        __syncthreads();
        uint32_t bs=sb+(uint32_t)(kc&1)*32768u;
        int gr8=((l>>4)&1)*8, kch=(l>>3)&1;
        #pragma unroll
        for(int kk=0;kk<2;++kk){
            uint32_t fbh[4][2],fbl[4][2];
            #pragma unroll
            for(int p=0;p<2;++p){
                uint32_t ba=bs+16384+off64(wn0+p*16+gr8+(l&7),kk*2+kch);
                uint32_t r[4];
                ldm4(r,ba);
                fbh[2*p][0]=r[0];fbh[2*p][1]=r[1];fbh[2*p+1][0]=r[2];fbh[2*p+1][1]=r[3];
                ldm4(r,ba+8192);
                fbl[2*p][0]=r[0];fbl[2*p][1]=r[1];fbl[2*p+1][0]=r[2];fbl[2*p+1][1]=r[3];
            }
            uint32_t fa[4][4];
            #pragma unroll
            for(int mi=0;mi<4;++mi)
                ldm4(fa[mi],bs+off64(wm0+mi*16+(l&15),kk*2+(l>>4)));
            #pragma unroll
            for(int mi=0;mi<4;++mi)
                #pragma unroll
                for(int ni=0;ni<4;++ni){
                    hmma(acc[mi][ni],fa[mi],fbh[ni]);
                    hmma(acc[mi][ni],fa[mi],fbl[ni]);
                }
            #pragma unroll
            for(int mi=0;mi<4;++mi)
                ldm4(fa[mi],bs+8192+off64(wm0+mi*16+(l&15),kk*2+(l>>4)));
            #pragma unroll
            for(int mi=0;mi<4;++mi)
                #pragma unroll
                for(int ni=0;ni<4;++ni)
                    hmma(acc[mi][ni],fa[mi],fbh[ni]);
        }
        __syncthreads();
    }

    int g=l>>2,t=l&3;
    if(MODE==0){
        float sc=(z==0)?0.125f:1.f;
        if(z<2){
            __nv_bfloat16* dh=z?g_ckh:g_qkh; __nv_bfloat16* dl=z?g_ckl:g_qkl;
            #pragma unroll
            for(int mi=0;mi<4;++mi)
                #pragma unroll
                for(int h2=0;h2<2;++h2){
                    int row=wm0+mi*16+g+h2*8;
                    long a=(long)(m0+row)*512+n0;
                    #pragma unroll
                    for(int ni=0;ni<4;++ni){
                        float v0=acc[mi][ni][h2*2]*sc, v1=acc[mi][ni][h2*2+1]*sc;
                        __nv_bfloat16 h0,lo0,h1,lo1; spl(v0,h0,lo0); spl(v1,h1,lo1);
                        int col=wn0+ni*8+2*t;
                        *(uint32_t*)(dh+a+col)=pk2(h0,h1);
                        *(uint32_t*)(dl+a+col)=pk2(lo0,lo1);
                    }
                }
        } else {
            __nv_bfloat16* dh=(z==2)?g_vth:g_cvh; __nv_bfloat16* dl=(z==2)?g_vtl:g_cvl;
            #pragma unroll
            for(int mi=0;mi<4;++mi)
                #pragma unroll
                for(int e=0;e<4;++e){
                    int row=m0+wm0+mi*16+g+(e>>1)*8;
                    int bb=row>>11, ii=row&2047;
                    #pragma unroll
                    for(int ni=0;ni<4;++ni){
                        int inner=n0+wn0+ni*8+2*t+(e&1);
                        long a=((long)((bb*8+(inner>>6))*64+(inner&63)))*N_+ii;
                        float v=acc[mi][ni][e];
                        __nv_bfloat16 h,lo;spl(v,h,lo);
                        dh[a]=h; dl[a]=lo;
                    }
                }
        }
    } else {
        const float* bias=z?bi1:bi0;
        #pragma unroll
        for(int mi=0;mi<4;++mi)
            #pragma unroll
            for(int h2=0;h2<2;++h2){
                int row=wm0+mi*16+g+h2*8;
                float* dst=outp+((long)z*MR+m0+row)*512+n0;
                #pragma unroll
                for(int ni=0;ni<4;++ni){
                    int col=wn0+ni*8+2*t;
                    float2 v;
                    v.x=acc[mi][ni][h2*2]+bias[n0+col];
                    v.y=acc[mi][ni][h2*2+1]+bias[n0+col+1];
                    *(float2*)(dst+col)=v;
                }
            }
    }
}

// ---------------- symmetric flash attention, both directions in one launch --
// Full 3-product sim (Q hi+lo). All tiles 128B rows, SW128.
constexpr int FQ=0;        // hi 16384, lo +16384
constexpr int FK=32768;    // hi 8192,  lo +8192
constexpr int FV=49152;    // hi 8192,  lo +8192
constexpr int FE=65536;    // hi 16384, lo +16384
constexpr int FR=98304;    // float[128]
constexpr int SMF2=98816;

__global__ void __launch_bounds__(256,2) fused2(){
    extern __shared__ __align__(16) char sm[];
    uint32_t sb=s2u(sm);
    int tid=threadIdx.x,w=tid>>5,l=tid&31;
    int it=blockIdx.x, z=blockIdx.y, dir=blockIdx.z;
    int bq=z>>3, hq=z&7;
    int i0=it*128;
    const __nv_bfloat16 *Qh_=dir?g_ckh:g_qkh, *Ql_=dir?g_ckl:g_qkl;
    const __nv_bfloat16 *Kh_=dir?g_qkh:g_ckh, *Kl_=dir?g_qkl:g_ckl;
    const __nv_bfloat16 *Vh_=dir?g_vth:g_cvh, *Vl_=dir?g_vtl:g_cvl;
    __nv_bfloat16 *Oh=dir?g_gh:g_oh, *Ol=dir?g_gl:g_ol;

    long qoff=((long)(bq*2048+i0))*512+hq*64;
    long kbase=((long)(bq*2048))*512+hq*64;
    long vbase=(long)z*64*2048;
    float* srow=(float*)(sm+FR);
    if(tid<128) srow[tid]=0.f;

    for(int c=tid;c<1024;c+=256){int r=c>>3,q=c&7;
        uint32_t o=swz((uint32_t)(r*128+q*16));
        cpa(sb+FQ+o,       Qh_+qoff+(long)r*512+q*8);
        cpa(sb+FQ+16384+o, Ql_+qoff+(long)r*512+q*8);}
    auto issue_k=[&](int jc){
        for(int c=tid;c<512;c+=256){int r=c>>3,q=c&7;
            uint32_t o=swz((uint32_t)(r*128+q*16));
            cpa(sb+FK+o,      Kh_+kbase+(long)(jc*64+r)*512+q*8);
            cpa(sb+FK+8192+o, Kl_+kbase+(long)(jc*64+r)*512+q*8);}
        asm volatile("cp.async.commit_group;");
    };
    auto issue_v=[&](int jc){
        for(int c=tid;c<512;c+=256){int r=c>>3,q=c&7;
            uint32_t o=swz((uint32_t)(r*128+q*16));
            cpa(sb+FV+o,      Vh_+vbase+(long)r*2048+jc*64+q*8);
            cpa(sb+FV+8192+o, Vl_+vbase+(long)r*2048+jc*64+q*8);}
        asm volatile("cp.async.commit_group;");
    };
    issue_k(0); issue_v(0);

    int g=l>>2,t=l&3;
    int wm=(w>>1)*32, wn=(w&1)*32;
    int gr8=((l>>4)&1)*8, kch=(l>>3)&1;
    float acc_o[2][4][4]; float rsum[2][2];
    #pragma unroll
    for(int i=0;i<2;i++)
        #pragma unroll
        for(int j=0;j<4;j++)
            #pragma unroll
            for(int e=0;e<4;e++)acc_o[i][j][e]=0.f;
    rsum[0][0]=rsum[0][1]=rsum[1][0]=rsum[1][1]=0.f;

    for(int jc=0;jc<32;++jc){
        asm volatile("cp.async.wait_group 1;");   // K(jc) (+Q at jc=0)
        __syncthreads();
        // ---- sim: Q(split) x K(split), 3 products, K=64 ----
        float s[2][4][4];
        #pragma unroll
        for(int i=0;i<2;i++)
            #pragma unroll
            for(int j=0;j<4;j++)
                #pragma unroll
                for(int e=0;e<4;e++)s[i][j][e]=0.f;
        #pragma unroll
        for(int kk=0;kk<4;++kk){
            uint32_t fbh[4][2],fbl[4][2];
            #pragma unroll
            for(int p=0;p<2;++p){
                uint32_t ba=sb+FK+swz((uint32_t)((wn+p*16+gr8+(l&7))*128+(kk*2+kch)*16));
                uint32_t r[4];
                ldm4(r,ba);
                fbh[2*p][0]=r[0];fbh[2*p][1]=r[1];fbh[2*p+1][0]=r[2];fbh[2*p+1][1]=r[3];
                ldm4(r,ba+8192);
                fbl[2*p][0]=r[0];fbl[2*p][1]=r[1];fbl[2*p+1][0]=r[2];fbl[2*p+1][1]=r[3];
            }
            uint32_t fa[2][4];
            #pragma unroll
            for(int mi=0;mi<2;++mi)
                ldm4(fa[mi],sb+FQ+swz((uint32_t)((wm+mi*16+(l&15))*128+(kk*2+(l>>4))*16)));
            #pragma unroll
            for(int mi=0;mi<2;++mi)
                #pragma unroll
                for(int ni=0;ni<4;++ni){
                    hmma(s[mi][ni],fa[mi],fbh[ni]);
                    hmma(s[mi][ni],fa[mi],fbl[ni]);
                }
            #pragma unroll
            for(int mi=0;mi<2;++mi)
                ldm4(fa[mi],sb+FQ+16384+swz((uint32_t)((wm+mi*16+(l&15))*128+(kk*2+(l>>4))*16)));
            #pragma unroll
            for(int mi=0;mi<2;++mi)
                #pragma unroll
                for(int ni=0;ni<4;++ni)
                    hmma(s[mi][ni],fa[mi],fbh[ni]);
        }
        // ---- exp -> E smem (hi+lo), rowsum in regs ----
        #pragma unroll
        for(int mi=0;mi<2;++mi)
            #pragma unroll
            for(int h2=0;h2<2;++h2){
                float rp=0.f;
                int row=wm+mi*16+g+h2*8;
                #pragma unroll
                for(int ni=0;ni<4;++ni){
                    float e0=fexp(s[mi][ni][h2*2]), e1=fexp(s[mi][ni][h2*2+1]);
                    rp+=e0+e1;
                    __nv_bfloat16 h0,lo0,h1,lo1; spl(e0,h0,lo0); spl(e1,h1,lo1);
                    uint32_t cb=swz((uint32_t)(row*128+(wn+ni*8+2*t)*2));
                    *(uint32_t*)(sm+FE+cb)=pk2(h0,h1);
                    *(uint32_t*)(sm+FE+16384+cb)=pk2(lo0,lo1);
                }
                rp+=__shfl_xor_sync(0xffffffffu,rp,1);
                rp+=__shfl_xor_sync(0xffffffffu,rp,2);
                rsum[mi][h2]+=rp;
            }
        __syncthreads();                           // E ready; K consumed
        if(jc+1<32){ issue_k(jc+1); asm volatile("cp.async.wait_group 1;"); }
        else asm volatile("cp.async.wait_group 0;");
        __syncthreads();                           // V(jc) visible
        // ---- out: acc_o += Eh@(Vh+Vl) + El@Vh, K=64 ----
        #pragma unroll
        for(int kk=0;kk<4;++kk){
            uint32_t gbh[4][2],gbl[4][2];
            #pragma unroll
            for(int p=0;p<2;++p){
                uint32_t ba=sb+FV+swz((uint32_t)((wn+p*16+gr8+(l&7))*128+(kk*2+kch)*16));
                uint32_t r[4];
                ldm4(r,ba);
                gbh[2*p][0]=r[0];gbh[2*p][1]=r[1];gbh[2*p+1][0]=r[2];gbh[2*p+1][1]=r[3];
                ldm4(r,ba+8192);
                gbl[2*p][0]=r[0];gbl[2*p][1]=r[1];gbl[2*p+1][0]=r[2];gbl[2*p+1][1]=r[3];
            }
            uint32_t fe[2][4];
            #pragma unroll
            for(int mi=0;mi<2;++mi)
                ldm4(fe[mi],sb+FE+swz((uint32_t)((wm+mi*16+(l&15))*128+(kk*2+(l>>4))*16)));
            #pragma unroll
            for(int mi=0;mi<2;++mi)
                #pragma unroll
                for(int ni=0;ni<4;++ni){
                    hmma(acc_o[mi][ni],fe[mi],gbh[ni]);
                    hmma(acc_o[mi][ni],fe[mi],gbl[ni]);
                }
            #pragma unroll
            for(int mi=0;mi<2;++mi)
                ldm4(fe[mi],sb+FE+16384+swz((uint32_t)((wm+mi*16+(l&15))*128+(kk*2+(l>>4))*16)));
            #pragma unroll
            for(int mi=0;mi<2;++mi)
                #pragma unroll
                for(int ni=0;ni<4;++ni)
                    hmma(acc_o[mi][ni],fe[mi],gbh[ni]);
        }
        __syncthreads();                           // V,E consumed
        if(jc+1<32) issue_v(jc+1);
    }
    // ---- rowsum combine, normalize, split-write ----
    #pragma unroll
    for(int mi=0;mi<2;++mi)
        #pragma unroll
        for(int h2=0;h2<2;++h2)
            if(t==0) atomicAdd(srow+wm+mi*16+g+h2*8,rsum[mi][h2]);
    __syncthreads();
    #pragma unroll
    for(int mi=0;mi<2;++mi)
        #pragma unroll
        for(int h2=0;h2<2;++h2){
            int row=wm+mi*16+g+h2*8;
            float inv=1.f/srow[row];
            long a=((long)(bq*2048+i0+row))*512+hq*64+wn;
            #pragma unroll
            for(int ni=0;ni<4;++ni){
                float v0=acc_o[mi][ni][h2*2]*inv, v1=acc_o[mi][ni][h2*2+1]*inv;
                __nv_bfloat16 h0,lo0,h1,lo1; spl(v0,h0,lo0); spl(v1,h1,lo1);
                *(uint32_t*)(Oh+a+ni*8+2*t)=pk2(h0,h1);
                *(uint32_t*)(Ol+a+ni*8+2*t)=pk2(lo0,lo1);
            }
        }
}

constexpr int SMBIG=65536;

extern "C" void kernel_launch(void* const* d_in,const int* in_sizes,int n_in,void* d_out,int out_size){
    (void)in_sizes;(void)n_in;(void)out_size;
    const float* x   =(const float*)d_in[0];
    const float* ctx =(const float*)d_in[1];
    const float* gx  =(const float*)d_in[2];
    const float* bx  =(const float*)d_in[3];
    const float* gc  =(const float*)d_in[4];
    const float* bc  =(const float*)d_in[5];
    const float* Wqk =(const float*)d_in[6];
    const float* Wcqk=(const float*)d_in[7];
    const float* Wv  =(const float*)d_in[8];
    const float* Wcv =(const float*)d_in[9];
    const float* Wout=(const float*)d_in[10];
    const float* bout=(const float*)d_in[11];
    const float* Wco =(const float*)d_in[12];
    const float* bco =(const float*)d_in[13];
    float* out=(float*)d_out;

    cudaFuncSetAttribute(mm_k<0>,cudaFuncAttributeMaxDynamicSharedMemorySize,SMBIG);
    cudaFuncSetAttribute(mm_k<4>,cudaFuncAttributeMaxDynamicSharedMemorySize,SMBIG);
    cudaFuncSetAttribute(fused2,cudaFuncAttributeMaxDynamicSharedMemorySize,SMF2);

    ln_k<<<MR,128>>>(x,gx,bx,0);
    ln_k<<<MR,128>>>(ctx,gc,bc,1);
    wsplit_k<<<dim3(16,16,6),dim3(32,32)>>>(Wqk,Wcqk,Wv,Wcv,Wout,Wco);
    mm_k<0><<<dim3(4,32,4),256,SMBIG>>>(nullptr,nullptr,nullptr);
    fused2<<<dim3(16,16,2),256,SMF2>>>();
    mm_k<4><<<dim3(4,32,2),256,SMBIG>>>(out,bout,bco);
}

// round 15
// speedup vs baseline: 1.3940x; 1.2469x over previous
#include <cuda_runtime.h>
#include <cuda_bf16.h>
#include <cuda_fp16.h>
#include <cstdint>

#define DI __device__ __forceinline__
constexpr int N_=2048, D_=512, MR=4096, WE=262144;

__device__ __nv_bfloat16 g_xnh[MR*D_],g_xnl[MR*D_],g_cnh[MR*D_],g_cnl[MR*D_];
__device__ __half g_qkh[MR*D_],g_qkl[MR*D_],g_ckh[MR*D_],g_ckl[MR*D_];
__device__ __half g_vth[MR*D_],g_vtl[MR*D_],g_cvh[MR*D_],g_cvl[MR*D_];
__device__ __nv_bfloat16 g_oh[MR*D_],g_ol[MR*D_],g_gh[MR*D_],g_gl[MR*D_];
__device__ __nv_bfloat16 g_wh[6*WE],g_wl[6*WE];

DI uint32_t s2u(const void* p){uint32_t a;asm("{ .reg .u64 t; cvta.to.shared.u64 t,%1; cvt.u32.u64 %0,t; }":"=r"(a):"l"(p));return a;}
DI void ldm4(uint32_t* r,uint32_t a){
    asm volatile("ldmatrix.sync.aligned.m8n8.x4.shared.b16 {%0,%1,%2,%3},[%4];"
        :"=r"(r[0]),"=r"(r[1]),"=r"(r[2]),"=r"(r[3]):"r"(a));
}
DI void hmma(float* c,const uint32_t* a,const uint32_t* b){
    asm volatile("mma.sync.aligned.m16n8k16.row.col.f32.bf16.bf16.f32 {%0,%1,%2,%3},{%4,%5,%6,%7},{%8,%9},{%0,%1,%2,%3};"
        :"+f"(c[0]),"+f"(c[1]),"+f"(c[2]),"+f"(c[3])
        :"r"(a[0]),"r"(a[1]),"r"(a[2]),"r"(a[3]),"r"(b[0]),"r"(b[1]));
}
DI void hmma_h(float* c,const uint32_t* a,const uint32_t* b){
    asm volatile("mma.sync.aligned.m16n8k16.row.col.f32.f16.f16.f32 {%0,%1,%2,%3},{%4,%5,%6,%7},{%8,%9},{%0,%1,%2,%3};"
        :"+f"(c[0]),"+f"(c[1]),"+f"(c[2]),"+f"(c[3])
        :"r"(a[0]),"r"(a[1]),"r"(a[2]),"r"(a[3]),"r"(b[0]),"r"(b[1]));
}
DI void cpa(uint32_t d,const void* s){asm volatile("cp.async.cg.shared.global [%0],[%1],16;"::"r"(d),"l"(s));}

DI uint32_t off64(int r,int q){return (uint32_t)(r*64+((q^((r>>1)&3))<<4));}
DI uint32_t swz(uint32_t o){return o^((o>>3)&0x70);}

DI float fexp(float x){
    x=fmaxf(x,-80.f); float t=x*1.4426950408889634f;
    float z=t+12582912.f, fi=z-12582912.f, f=t-fi;
    int i=__float_as_int(z)-0x4B400000;
    float p=1.3333558146428443e-3f;
    p=fmaf(p,f,9.618129107628477e-3f); p=fmaf(p,f,5.550410866482158e-2f);
    p=fmaf(p,f,2.402265069591007e-1f); p=fmaf(p,f,6.931471805599453e-1f);
    p=fmaf(p,f,1.0f);
    return __int_as_float(__float_as_int(p)+(i<<23));
}
DI void spl(float v,__nv_bfloat16&h,__nv_bfloat16&l){h=__float2bfloat16(v);l=__float2bfloat16(v-__bfloat162float(h));}
DI void splh(float v,__half&h,__half&l){h=__float2half(v);l=__float2half(v-__half2float(h));}
DI uint32_t pk2(__nv_bfloat16 a,__nv_bfloat16 b){return ((uint32_t)__bfloat16_as_ushort(b)<<16)|(uint32_t)__bfloat16_as_ushort(a);}
DI uint32_t pk2h(__half a,__half b){return ((uint32_t)__half_as_ushort(b)<<16)|(uint32_t)__half_as_ushort(a);}

DI float wred(float v){
    #pragma unroll
    for(int o=16;o>0;o>>=1)v+=__shfl_xor_sync(0xffffffffu,v,o);
    return v;
}
__global__ void ln_k(const float* __restrict__ x,const float* __restrict__ g,const float* __restrict__ b,int which){
    __shared__ float sh[8];
    long row=blockIdx.x;
    float4 v=((const float4*)(x+row*D_))[threadIdx.x];
    float s=v.x+v.y+v.z+v.w, sq=v.x*v.x+v.y*v.y+v.z*v.z+v.w*v.w;
    int l=threadIdx.x&31,w=threadIdx.x>>5;
    s=wred(s);sq=wred(sq);
    if(l==0){sh[w]=s;sh[4+w]=sq;}
    __syncthreads();
    s=sh[0]+sh[1]+sh[2]+sh[3]; sq=sh[4]+sh[5]+sh[6]+sh[7];
    float mu=s/D_, rstd=rsqrtf(sq/D_-mu*mu+1e-5f);
    float4 gg=((const float4*)g)[threadIdx.x], bb=((const float4*)b)[threadIdx.x];
    float o0=(v.x-mu)*rstd*gg.x+bb.x, o1=(v.y-mu)*rstd*gg.y+bb.y;
    float o2=(v.z-mu)*rstd*gg.z+bb.z, o3=(v.w-mu)*rstd*gg.w+bb.w;
    __nv_bfloat16 h0,h1,h2,h3,l0,l1,l2,l3;
    spl(o0,h0,l0);spl(o1,h1,l1);spl(o2,h2,l2);spl(o3,h3,l3);
    __nv_bfloat16* dh=which?g_cnh:g_xnh; __nv_bfloat16* dl=which?g_cnl:g_xnl;
    long a=row*D_+threadIdx.x*4;
    *(uint2*)(dh+a)=make_uint2(pk2(h0,h1),pk2(h2,h3));
    *(uint2*)(dl+a)=make_uint2(pk2(l0,l1),pk2(l2,l3));
}
__global__ void wsplit_k(const float* w0,const float* w1,const float* w2,const float* w3,const float* w4,const float* w5){
    __shared__ float t[32][33];
    int z=blockIdx.z;
    const float* W=(z==0)?w0:(z==1)?w1:(z==2)?w2:(z==3)?w3:(z==4)?w4:w5;
    int n0=blockIdx.x*32,k0=blockIdx.y*32,tx=threadIdx.x,ty=threadIdx.y;
    t[ty][tx]=W[(long)(k0+ty)*512+n0+tx];
    __syncthreads();
    float v=t[tx][ty];
    long a=(long)z*WE+(long)(n0+ty)*512+k0+tx;
    __nv_bfloat16 h,l;spl(v,h,l); g_wh[a]=h;g_wl[a]=l;
}

// MODE 0: input projections (z: 0 qk,1 cqk,2 v,3 cv)   MODE 4: final proj
template<int MODE>
__global__ void __launch_bounds__(256,2) mm_k(float* outp,const float* bi0,const float* bi1){
    extern __shared__ __align__(16) char sm[];
    constexpr int NCH=16;
    uint32_t sb=s2u(sm);
    int tid=threadIdx.x,w=tid>>5,l=tid&31,z=blockIdx.z;
    int m0=blockIdx.y*128, n0=blockIdx.x*128;
    int wm0=(w>>2)*64, wn0=(w&3)*32;

    const __nv_bfloat16 *Ah,*Al,*Bh,*Bl;
    if(MODE==0){
        Ah=((z&1)?g_cnh:g_xnh)+(long)m0*512; Al=((z&1)?g_cnl:g_xnl)+(long)m0*512;
        Bh=g_wh+(long)z*WE+(long)n0*512; Bl=g_wl+(long)z*WE+(long)n0*512;
    } else {
        Ah=(z?g_gh:g_oh)+(long)m0*512; Al=(z?g_gl:g_ol)+(long)m0*512;
        Bh=g_wh+(long)(4+z)*WE+(long)n0*512; Bl=g_wl+(long)(4+z)*WE+(long)n0*512;
    }
    float acc[4][4][4];
    #pragma unroll
    for(int i=0;i<4;i++)
        #pragma unroll
        for(int j=0;j<4;j++)
            #pragma unroll
            for(int e=0;e<4;e++)acc[i][j][e]=0.f;

    auto issue=[&](int kc){
        uint32_t bs=sb+(uint32_t)(kc&1)*32768u;
        const __nv_bfloat16* a=Ah+kc*32; const __nv_bfloat16* a2=Al+kc*32;
        for(int c=tid;c<512;c+=256){int r=c>>2,q=c&3;
            uint32_t o=off64(r,q);
            cpa(bs+o,a+(long)r*512+q*8);
            cpa(bs+8192+o,a2+(long)r*512+q*8);}
        const __nv_bfloat16* b=Bh+kc*32; const __nv_bfloat16* b2=Bl+kc*32;
        for(int c=tid;c<512;c+=256){int r=c>>2,q=c&3;
            uint32_t o=off64(r,q);
            cpa(bs+16384+o,b+(long)r*512+q*8);
            cpa(bs+24576+o,b2+(long)r*512+q*8);}
        asm volatile("cp.async.commit_group;");
    };

    issue(0);
    for(int kc=0;kc<NCH;++kc){
        if(kc+1<NCH){issue(kc+1); asm volatile("cp.async.wait_group 1;");}
        else asm volatile("cp.async.wait_group 0;");
        __syncthreads();
        uint32_t bs=sb+(uint32_t)(kc&1)*32768u;
        int gr8=((l>>4)&1)*8, kch=(l>>3)&1;
        #pragma unroll
        for(int kk=0;kk<2;++kk){
            uint32_t fbh[4][2],fbl[4][2];
            #pragma unroll
            for(int p=0;p<2;++p){
                uint32_t ba=bs+16384+off64(wn0+p*16+gr8+(l&7),kk*2+kch);
                uint32_t r[4];
                ldm4(r,ba);
                fbh[2*p][0]=r[0];fbh[2*p][1]=r[1];fbh[2*p+1][0]=r[2];fbh[2*p+1][1]=r[3];
                ldm4(r,ba+8192);
                fbl[2*p][0]=r[0];fbl[2*p][1]=r[1];fbl[2*p+1][0]=r[2];fbl[2*p+1][1]=r[3];
            }
            uint32_t fa[4][4];
            #pragma unroll
            for(int mi=0;mi<4;++mi)
                ldm4(fa[mi],bs+off64(wm0+mi*16+(l&15),kk*2+(l>>4)));
            #pragma unroll
            for(int mi=0;mi<4;++mi)
                #pragma unroll
                for(int ni=0;ni<4;++ni){
                    hmma(acc[mi][ni],fa[mi],fbh[ni]);
                    hmma(acc[mi][ni],fa[mi],fbl[ni]);
                }
            #pragma unroll
            for(int mi=0;mi<4;++mi)
                ldm4(fa[mi],bs+8192+off64(wm0+mi*16+(l&15),kk*2+(l>>4)));
            #pragma unroll
            for(int mi=0;mi<4;++mi)
                #pragma unroll
                for(int ni=0;ni<4;++ni)
                    hmma(acc[mi][ni],fa[mi],fbh[ni]);
        }
        __syncthreads();
    }

    int g=l>>2,t=l&3;
    if(MODE==0){
        float sc=(z==0)?0.125f:1.f;
        if(z<2){
            __half* dh=z?g_ckh:g_qkh; __half* dl=z?g_ckl:g_qkl;
            #pragma unroll
            for(int mi=0;mi<4;++mi)
                #pragma unroll
                for(int h2=0;h2<2;++h2){
                    int row=wm0+mi*16+g+h2*8;
                    long a=(long)(m0+row)*512+n0;
                    #pragma unroll
                    for(int ni=0;ni<4;++ni){
                        float v0=acc[mi][ni][h2*2]*sc, v1=acc[mi][ni][h2*2+1]*sc;
                        __half h0,lo0,h1,lo1; splh(v0,h0,lo0); splh(v1,h1,lo1);
                        int col=wn0+ni*8+2*t;
                        *(uint32_t*)(dh+a+col)=pk2h(h0,h1);
                        *(uint32_t*)(dl+a+col)=pk2h(lo0,lo1);
                    }
                }
        } else {
            __half* dh=(z==2)?g_vth:g_cvh; __half* dl=(z==2)?g_vtl:g_cvl;
            #pragma unroll
            for(int mi=0;mi<4;++mi)
                #pragma unroll
                for(int e=0;e<4;++e){
                    int row=m0+wm0+mi*16+g+(e>>1)*8;
                    int bb=row>>11, ii=row&2047;
                    #pragma unroll
                    for(int ni=0;ni<4;++ni){
                        int inner=n0+wn0+ni*8+2*t+(e&1);
                        long a=((long)((bb*8+(inner>>6))*64+(inner&63)))*N_+ii;
                        float v=acc[mi][ni][e];
                        __half h,lo;splh(v,h,lo);
                        dh[a]=h; dl[a]=lo;
                    }
                }
        }
    } else {
        const float* bias=z?bi1:bi0;
        #pragma unroll
        for(int mi=0;mi<4;++mi)
            #pragma unroll
            for(int h2=0;h2<2;++h2){
                int row=wm0+mi*16+g+h2*8;
                float* dst=outp+((long)z*MR+m0+row)*512+n0;
                #pragma unroll
                for(int ni=0;ni<4;++ni){
                    int col=wn0+ni*8+2*t;
                    float2 v;
                    v.x=acc[mi][ni][h2*2]+bias[n0+col];
                    v.y=acc[mi][ni][h2*2+1]+bias[n0+col+1];
                    *(float2*)(dst+col)=v;
                }
            }
    }
}

// ---------------- symmetric flash attention, both directions, fp16 ---------
// sim = Qh @ (Kh+Kl), 2 products; E single fp16; out = E @ (Vh+Vl), 2 products.
constexpr int FQ=0;        // 16384 (Q hi only)
constexpr int FK=16384;    // hi 8192, lo +8192
constexpr int FV=32768;    // hi 8192, lo +8192
constexpr int FE=49152;    // 16384 (single)
constexpr int FR=65536;    // float[128]
constexpr int SMF2=66048;

__global__ void __launch_bounds__(256,2) fused2(){
    extern __shared__ __align__(16) char sm[];
    uint32_t sb=s2u(sm);
    int tid=threadIdx.x,w=tid>>5,l=tid&31;
    int it=blockIdx.x, z=blockIdx.y, dir=blockIdx.z;
    int bq=z>>3, hq=z&7;
    int i0=it*128;
    const __half *Qh_=dir?g_ckh:g_qkh;
    const __half *Kh_=dir?g_qkh:g_ckh, *Kl_=dir?g_qkl:g_ckl;
    const __half *Vh_=dir?g_vth:g_cvh, *Vl_=dir?g_vtl:g_cvl;
    __nv_bfloat16 *Oh=dir?g_gh:g_oh, *Ol=dir?g_gl:g_ol;

    long qoff=((long)(bq*2048+i0))*512+hq*64;
    long kbase=((long)(bq*2048))*512+hq*64;
    long vbase=(long)z*64*2048;
    float* srow=(float*)(sm+FR);
    if(tid<128) srow[tid]=0.f;

    for(int c=tid;c<1024;c+=256){int r=c>>3,q=c&7;
        cpa(sb+FQ+swz((uint32_t)(r*128+q*16)), Qh_+qoff+(long)r*512+q*8);}
    auto issue_k=[&](int jc){
        for(int c=tid;c<512;c+=256){int r=c>>3,q=c&7;
            uint32_t o=swz((uint32_t)(r*128+q*16));
            cpa(sb+FK+o,      Kh_+kbase+(long)(jc*64+r)*512+q*8);
            cpa(sb+FK+8192+o, Kl_+kbase+(long)(jc*64+r)*512+q*8);}
        asm volatile("cp.async.commit_group;");
    };
    auto issue_v=[&](int jc){
        for(int c=tid;c<512;c+=256){int r=c>>3,q=c&7;
            uint32_t o=swz((uint32_t)(r*128+q*16));
            cpa(sb+FV+o,      Vh_+vbase+(long)r*2048+jc*64+q*8);
            cpa(sb+FV+8192+o, Vl_+vbase+(long)r*2048+jc*64+q*8);}
        asm volatile("cp.async.commit_group;");
    };
    issue_k(0); issue_v(0);

    int g=l>>2,t=l&3;
    int wm=(w>>1)*32, wn=(w&1)*32;
    int gr8=((l>>4)&1)*8, kch=(l>>3)&1;
    float acc_o[2][4][4]; float rsum[2][2];
    #pragma unroll
    for(int i=0;i<2;i++)
        #pragma unroll
        for(int j=0;j<4;j++)
            #pragma unroll
            for(int e=0;e<4;e++)acc_o[i][j][e]=0.f;
    rsum[0][0]=rsum[0][1]=rsum[1][0]=rsum[1][1]=0.f;

    for(int jc=0;jc<32;++jc){
        asm volatile("cp.async.wait_group 1;");   // K(jc) (+Q at jc=0)
        __syncthreads();
        // ---- sim: Qh x (Kh+Kl), 2 products, K=64 ----
        float s[2][4][4];
        #pragma unroll
        for(int i=0;i<2;i++)
            #pragma unroll
            for(int j=0;j<4;j++)
                #pragma unroll
                for(int e=0;e<4;e++)s[i][j][e]=0.f;
        #pragma unroll
        for(int kk=0;kk<4;++kk){
            uint32_t fbh[4][2],fbl[4][2];
            #pragma unroll
            for(int p=0;p<2;++p){
                uint32_t ba=sb+FK+swz((uint32_t)((wn+p*16+gr8+(l&7))*128+(kk*2+kch)*16));
                uint32_t r[4];
                ldm4(r,ba);
                fbh[2*p][0]=r[0];fbh[2*p][1]=r[1];fbh[2*p+1][0]=r[2];fbh[2*p+1][1]=r[3];
                ldm4(r,ba+8192);
                fbl[2*p][0]=r[0];fbl[2*p][1]=r[1];fbl[2*p+1][0]=r[2];fbl[2*p+1][1]=r[3];
            }
            uint32_t fa[2][4];
            #pragma unroll
            for(int mi=0;mi<2;++mi)
                ldm4(fa[mi],sb+FQ+swz((uint32_t)((wm+mi*16+(l&15))*128+(kk*2+(l>>4))*16)));
            #pragma unroll
            for(int mi=0;mi<2;++mi)
                #pragma unroll
                for(int ni=0;ni<4;++ni){
                    hmma_h(s[mi][ni],fa[mi],fbh[ni]);
                    hmma_h(s[mi][ni],fa[mi],fbl[ni]);
                }
        }
        // ---- exp -> E smem (single fp16), rowsum in regs ----
        #pragma unroll
        for(int mi=0;mi<2;++mi)
            #pragma unroll
            for(int h2=0;h2<2;++h2){
                float rp=0.f;
                int row=wm+mi*16+g+h2*8;
                #pragma unroll
                for(int ni=0;ni<4;++ni){
                    float e0=fexp(s[mi][ni][h2*2]), e1=fexp(s[mi][ni][h2*2+1]);
                    rp+=e0+e1;
                    uint32_t cb=swz((uint32_t)(row*128+(wn+ni*8+2*t)*2));
                    *(uint32_t*)(sm+FE+cb)=pk2h(__float2half(e0),__float2half(e1));
                }
                rp+=__shfl_xor_sync(0xffffffffu,rp,1);
                rp+=__shfl_xor_sync(0xffffffffu,rp,2);
                rsum[mi][h2]+=rp;
            }
        __syncthreads();                           // E ready; K consumed
        if(jc+1<32){ issue_k(jc+1); asm volatile("cp.async.wait_group 1;"); }
        else asm volatile("cp.async.wait_group 0;");
        __syncthreads();                           // V(jc) visible
        // ---- out: acc_o += E @ (Vh+Vl), 2 products, K=64 ----
        #pragma unroll
        for(int kk=0;kk<4;++kk){
            uint32_t gbh[4][2],gbl[4][2];
            #pragma unroll
            for(int p=0;p<2;++p){
                uint32_t ba=sb+FV+swz((uint32_t)((wn+p*16+gr8+(l&7))*128+(kk*2+kch)*16));
                uint32_t r[4];
                ldm4(r,ba);
                gbh[2*p][0]=r[0];gbh[2*p][1]=r[1];gbh[2*p+1][0]=r[2];gbh[2*p+1][1]=r[3];
                ldm4(r,ba+8192);
                gbl[2*p][0]=r[0];gbl[2*p][1]=r[1];gbl[2*p+1][0]=r[2];gbl[2*p+1][1]=r[3];
            }
            uint32_t fe[2][4];
            #pragma unroll
            for(int mi=0;mi<2;++mi)
                ldm4(fe[mi],sb+FE+swz((uint32_t)((wm+mi*16+(l&15))*128+(kk*2+(l>>4))*16)));
            #pragma unroll
            for(int mi=0;mi<2;++mi)
                #pragma unroll
                for(int ni=0;ni<4;++ni){
                    hmma_h(acc_o[mi][ni],fe[mi],gbh[ni]);
                    hmma_h(acc_o[mi][ni],fe[mi],gbl[ni]);
                }
        }
        __syncthreads();                           // V,E consumed
        if(jc+1<32) issue_v(jc+1);
    }
    // ---- rowsum combine, normalize, split-write (bf16, for final proj) ----
    #pragma unroll
    for(int mi=0;mi<2;++mi)
        #pragma unroll
        for(int h2=0;h2<2;++h2)
            if(t==0) atomicAdd(srow+wm+mi*16+g+h2*8,rsum[mi][h2]);
    __syncthreads();
    #pragma unroll
    for(int mi=0;mi<2;++mi)
        #pragma unroll
        for(int h2=0;h2<2;++h2){
            int row=wm+mi*16+g+h2*8;
            float inv=1.f/srow[row];
            long a=((long)(bq*2048+i0+row))*512+hq*64+wn;
            #pragma unroll
            for(int ni=0;ni<4;++ni){
                float v0=acc_o[mi][ni][h2*2]*inv, v1=acc_o[mi][ni][h2*2+1]*inv;
                __nv_bfloat16 h0,lo0,h1,lo1; spl(v0,h0,lo0); spl(v1,h1,lo1);
                *(uint32_t*)(Oh+a+ni*8+2*t)=pk2(h0,h1);
                *(uint32_t*)(Ol+a+ni*8+2*t)=pk2(lo0,lo1);
            }
        }
}

constexpr int SMBIG=65536;

extern "C" void kernel_launch(void* const* d_in,const int* in_sizes,int n_in,void* d_out,int out_size){
    (void)in_sizes;(void)n_in;(void)out_size;
    const float* x   =(const float*)d_in[0];
    const float* ctx =(const float*)d_in[1];
    const float* gx  =(const float*)d_in[2];
    const float* bx  =(const float*)d_in[3];
    const float* gc  =(const float*)d_in[4];
    const float* bc  =(const float*)d_in[5];
    const float* Wqk =(const float*)d_in[6];
    const float* Wcqk=(const float*)d_in[7];
    const float* Wv  =(const float*)d_in[8];
    const float* Wcv =(const float*)d_in[9];
    const float* Wout=(const float*)d_in[10];
    const float* bout=(const float*)d_in[11];
    const float* Wco =(const float*)d_in[12];
    const float* bco =(const float*)d_in[13];
    float* out=(float*)d_out;

    cudaFuncSetAttribute(mm_k<0>,cudaFuncAttributeMaxDynamicSharedMemorySize,SMBIG);
    cudaFuncSetAttribute(mm_k<4>,cudaFuncAttributeMaxDynamicSharedMemorySize,SMBIG);
    cudaFuncSetAttribute(fused2,cudaFuncAttributeMaxDynamicSharedMemorySize,SMF2);

    ln_k<<<MR,128>>>(x,gx,bx,0);
    ln_k<<<MR,128>>>(ctx,gc,bc,1);
    wsplit_k<<<dim3(16,16,6),dim3(32,32)>>>(Wqk,Wcqk,Wv,Wcv,Wout,Wco);
    mm_k<0><<<dim3(4,32,4),256,SMBIG>>>(nullptr,nullptr,nullptr);
    fused2<<<dim3(16,16,2),256,SMF2>>>();
    mm_k<4><<<dim3(4,32,2),256,SMBIG>>>(out,bout,bco);
}

// round 17
// speedup vs baseline: 1.5490x; 1.1112x over previous
#include <cuda_runtime.h>
#include <cuda_fp16.h>
#include <cstdint>

#define DI __device__ __forceinline__
constexpr int N_=2048, D_=512, MR=4096, WE=262144;

__device__ __half g_xnh[MR*D_],g_cnh[MR*D_];
__device__ __half g_qkh[MR*D_],g_qkl[MR*D_],g_ckh[MR*D_],g_ckl[MR*D_];
__device__ __half g_vth[MR*D_],g_vtl[MR*D_],g_cvh[MR*D_],g_cvl[MR*D_];
__device__ __half g_oh[MR*D_],g_gh[MR*D_];
__device__ __half g_wh[6*WE],g_wl[6*WE];

DI uint32_t s2u(const void* p){uint32_t a;asm("{ .reg .u64 t; cvta.to.shared.u64 t,%1; cvt.u32.u64 %0,t; }":"=r"(a):"l"(p));return a;}
DI void ldm4(uint32_t* r,uint32_t a){
    asm volatile("ldmatrix.sync.aligned.m8n8.x4.shared.b16 {%0,%1,%2,%3},[%4];"
        :"=r"(r[0]),"=r"(r[1]),"=r"(r[2]),"=r"(r[3]):"r"(a));
}
DI void hmma_h(float* c,const uint32_t* a,const uint32_t* b){
    asm volatile("mma.sync.aligned.m16n8k16.row.col.f32.f16.f16.f32 {%0,%1,%2,%3},{%4,%5,%6,%7},{%8,%9},{%0,%1,%2,%3};"
        :"+f"(c[0]),"+f"(c[1]),"+f"(c[2]),"+f"(c[3])
        :"r"(a[0]),"r"(a[1]),"r"(a[2]),"r"(a[3]),"r"(b[0]),"r"(b[1]));
}
DI void cpa(uint32_t d,const void* s){asm volatile("cp.async.cg.shared.global [%0],[%1],16;"::"r"(d),"l"(s));}

DI uint32_t off64(int r,int q){return (uint32_t)(r*64+((q^((r>>1)&3))<<4));}
DI uint32_t swz(uint32_t o){return o^((o>>3)&0x70);}

DI float fexp(float x){
    x=fmaxf(x,-80.f); float t=x*1.4426950408889634f;
    float z=t+12582912.f, fi=z-12582912.f, f=t-fi;
    int i=__float_as_int(z)-0x4B400000;
    float p=1.3333558146428443e-3f;
    p=fmaf(p,f,9.618129107628477e-3f); p=fmaf(p,f,5.550410866482158e-2f);
    p=fmaf(p,f,2.402265069591007e-1f); p=fmaf(p,f,6.931471805599453e-1f);
    p=fmaf(p,f,1.0f);
    return __int_as_float(__float_as_int(p)+(i<<23));
}
DI void splh(float v,__half&h,__half&l){h=__float2half(v);l=__float2half(v-__half2float(h));}
DI uint32_t pk2h(__half a,__half b){return ((uint32_t)__half_as_ushort(b)<<16)|(uint32_t)__half_as_ushort(a);}

DI float wred(float v){
    #pragma unroll
    for(int o=16;o>0;o>>=1)v+=__shfl_xor_sync(0xffffffffu,v,o);
    return v;
}
__global__ void ln_k(const float* __restrict__ x,const float* __restrict__ g,const float* __restrict__ b,int which){
    __shared__ float sh[8];
    long row=blockIdx.x;
    float4 v=((const float4*)(x+row*D_))[threadIdx.x];
    float s=v.x+v.y+v.z+v.w, sq=v.x*v.x+v.y*v.y+v.z*v.z+v.w*v.w;
    int l=threadIdx.x&31,w=threadIdx.x>>5;
    s=wred(s);sq=wred(sq);
    if(l==0){sh[w]=s;sh[4+w]=sq;}
    __syncthreads();
    s=sh[0]+sh[1]+sh[2]+sh[3]; sq=sh[4]+sh[5]+sh[6]+sh[7];
    float mu=s/D_, rstd=rsqrtf(sq/D_-mu*mu+1e-5f);
    float4 gg=((const float4*)g)[threadIdx.x], bb=((const float4*)b)[threadIdx.x];
    float o0=(v.x-mu)*rstd*gg.x+bb.x, o1=(v.y-mu)*rstd*gg.y+bb.y;
    float o2=(v.z-mu)*rstd*gg.z+bb.z, o3=(v.w-mu)*rstd*gg.w+bb.w;
    __half* dh=which?g_cnh:g_xnh;
    long a=row*D_+threadIdx.x*4;
    *(uint2*)(dh+a)=make_uint2(pk2h(__float2half(o0),__float2half(o1)),
                               pk2h(__float2half(o2),__float2half(o3)));
}
__global__ void wsplit_k(const float* w0,const float* w1,const float* w2,const float* w3,const float* w4,const float* w5){
    __shared__ float t[32][33];
    int z=blockIdx.z;
    const float* W=(z==0)?w0:(z==1)?w1:(z==2)?w2:(z==3)?w3:(z==4)?w4:w5;
    int n0=blockIdx.x*32,k0=blockIdx.y*32,tx=threadIdx.x,ty=threadIdx.y;
    t[ty][tx]=W[(long)(k0+ty)*512+n0+tx];
    __syncthreads();
    float v=t[tx][ty];
    long a=(long)z*WE+(long)(n0+ty)*512+k0+tx;
    __half h,l;splh(v,h,l); g_wh[a]=h;g_wl[a]=l;
}

// MODE 0: input projections (z: 0 qk,1 cqk,2 v,3 cv)   MODE 4: final proj
// fp16: A single, B hi+lo, 2 products.  Stage: A 8K | Bh 8K | Bl 8K = 24K; x2 = 48K
template<int MODE>
__global__ void __launch_bounds__(256,2) mm_k(float* outp,const float* bi0,const float* bi1){
    extern __shared__ __align__(16) char sm[];
    constexpr int NCH=16;
    uint32_t sb=s2u(sm);
    int tid=threadIdx.x,w=tid>>5,l=tid&31,z=blockIdx.z;
    int m0=blockIdx.y*128, n0=blockIdx.x*128;
    int wm0=(w>>2)*64, wn0=(w&3)*32;

    const __half *A,*Bh,*Bl;
    if(MODE==0){
        A=((z&1)?g_cnh:g_xnh)+(long)m0*512;
        Bh=g_wh+(long)z*WE+(long)n0*512; Bl=g_wl+(long)z*WE+(long)n0*512;
    } else {
        A=(z?g_gh:g_oh)+(long)m0*512;
        Bh=g_wh+(long)(4+z)*WE+(long)n0*512; Bl=g_wl+(long)(4+z)*WE+(long)n0*512;
    }
    float acc[4][4][4];
    #pragma unroll
    for(int i=0;i<4;i++)
        #pragma unroll
        for(int j=0;j<4;j++)
            #pragma unroll
            for(int e=0;e<4;e++)acc[i][j][e]=0.f;

    auto issue=[&](int kc){
        uint32_t bs=sb+(uint32_t)(kc&1)*24576u;
        const __half* a=A+kc*32;
        for(int c=tid;c<512;c+=256){int r=c>>2,q=c&3;
            cpa(bs+off64(r,q),a+(long)r*512+q*8);}
        const __half* b=Bh+kc*32; const __half* b2=Bl+kc*32;
        for(int c=tid;c<512;c+=256){int r=c>>2,q=c&3;
            uint32_t o=off64(r,q);
            cpa(bs+8192+o,b+(long)r*512+q*8);
            cpa(bs+16384+o,b2+(long)r*512+q*8);}
        asm volatile("cp.async.commit_group;");
    };

    issue(0);
    for(int kc=0;kc<NCH;++kc){
        if(kc+1<NCH){issue(kc+1); asm volatile("cp.async.wait_group 1;");}
        else asm volatile("cp.async.wait_group 0;");
        __syncthreads();
        uint32_t bs=sb+(uint32_t)(kc&1)*24576u;
        int gr8=((l>>4)&1)*8, kch=(l>>3)&1;
        #pragma unroll
        for(int kk=0;kk<2;++kk){
            uint32_t fbh[4][2],fbl[4][2];
            #pragma unroll
            for(int p=0;p<2;++p){
                uint32_t ba=bs+8192+off64(wn0+p*16+gr8+(l&7),kk*2+kch);
                uint32_t r[4];
                ldm4(r,ba);
                fbh[2*p][0]=r[0];fbh[2*p][1]=r[1];fbh[2*p+1][0]=r[2];fbh[2*p+1][1]=r[3];
                ldm4(r,ba+8192);
                fbl[2*p][0]=r[0];fbl[2*p][1]=r[1];fbl[2*p+1][0]=r[2];fbl[2*p+1][1]=r[3];
            }
            uint32_t fa[4][4];
            #pragma unroll
            for(int mi=0;mi<4;++mi)
                ldm4(fa[mi],bs+off64(wm0+mi*16+(l&15),kk*2+(l>>4)));
            #pragma unroll
            for(int mi=0;mi<4;++mi)
                #pragma unroll
                for(int ni=0;ni<4;++ni){
                    hmma_h(acc[mi][ni],fa[mi],fbh[ni]);
                    hmma_h(acc[mi][ni],fa[mi],fbl[ni]);
                }
        }
        __syncthreads();
    }

    int g=l>>2,t=l&3;
    if(MODE==0){
        float sc=(z==0)?0.125f:1.f;
        if(z<2){
            __half* dh=z?g_ckh:g_qkh; __half* dl=z?g_ckl:g_qkl;
            #pragma unroll
            for(int mi=0;mi<4;++mi)
                #pragma unroll
                for(int h2=0;h2<2;++h2){
                    int row=wm0+mi*16+g+h2*8;
                    long a=(long)(m0+row)*512+n0;
                    #pragma unroll
                    for(int ni=0;ni<4;++ni){
                        float v0=acc[mi][ni][h2*2]*sc, v1=acc[mi][ni][h2*2+1]*sc;
                        __half h0,lo0,h1,lo1; splh(v0,h0,lo0); splh(v1,h1,lo1);
                        int col=wn0+ni*8+2*t;
                        *(uint32_t*)(dh+a+col)=pk2h(h0,h1);
                        *(uint32_t*)(dl+a+col)=pk2h(lo0,lo1);
                    }
                }
        } else {
            __half* dh=(z==2)?g_vth:g_cvh; __half* dl=(z==2)?g_vtl:g_cvl;
            #pragma unroll
            for(int mi=0;mi<4;++mi)
                #pragma unroll
                for(int e=0;e<4;++e){
                    int row=m0+wm0+mi*16+g+(e>>1)*8;
                    int bb=row>>11, ii=row&2047;
                    #pragma unroll
                    for(int ni=0;ni<4;++ni){
                        int inner=n0+wn0+ni*8+2*t+(e&1);
                        long a=((long)((bb*8+(inner>>6))*64+(inner&63)))*N_+ii;
                        float v=acc[mi][ni][e];
                        __half h,lo;splh(v,h,lo);
                        dh[a]=h; dl[a]=lo;
                    }
                }
        }
    } else {
        const float* bias=z?bi1:bi0;
        #pragma unroll
        for(int mi=0;mi<4;++mi)
            #pragma unroll
            for(int h2=0;h2<2;++h2){
                int row=wm0+mi*16+g+h2*8;
                float* dst=outp+((long)z*MR+m0+row)*512+n0;
                #pragma unroll
                for(int ni=0;ni<4;++ni){
                    int col=wn0+ni*8+2*t;
                    float2 v;
                    v.x=acc[mi][ni][h2*2]+bias[n0+col];
                    v.y=acc[mi][ni][h2*2+1]+bias[n0+col+1];
                    *(float2*)(dst+col)=v;
                }
            }
    }
}

// ---------------- symmetric flash attention, both dirs, fp16, dbl-buffered --
// sim = Qh @ (Kh+Kl); E single fp16; out = E @ (Vh+Vl).
constexpr int FQ=0;        // 16384 (Q hi only)
constexpr int FK=16384;    // 2 bufs x (hi 8192 + lo 8192)
constexpr int FV=49152;    // 2 bufs x (hi 8192 + lo 8192)
constexpr int FE=81920;    // 16384 (single)
constexpr int FR=98304;    // float[128]
constexpr int SMF2=98816;

__global__ void __launch_bounds__(256,2) fused2(){
    extern __shared__ __align__(16) char sm[];
    uint32_t sb=s2u(sm);
    int tid=threadIdx.x,w=tid>>5,l=tid&31;
    int it=blockIdx.x, z=blockIdx.y, dir=blockIdx.z;
    int bq=z>>3, hq=z&7;
    int i0=it*128;
    const __half *Qh_=dir?g_ckh:g_qkh;
    const __half *Kh_=dir?g_qkh:g_ckh, *Kl_=dir?g_qkl:g_ckl;
    const __half *Vh_=dir?g_vth:g_cvh, *Vl_=dir?g_vtl:g_cvl;
    __half *Oh=dir?g_gh:g_oh;

    long qoff=((long)(bq*2048+i0))*512+hq*64;
    long kbase=((long)(bq*2048))*512+hq*64;
    long vbase=(long)z*64*2048;
    float* srow=(float*)(sm+FR);
    if(tid<128) srow[tid]=0.f;

    auto issue=[&](int jc){
        uint32_t kb=sb+FK+(uint32_t)(jc&1)*16384u;
        uint32_t vb=sb+FV+(uint32_t)(jc&1)*16384u;
        for(int c=tid;c<512;c+=256){int r=c>>3,q=c&7;
            uint32_t o=swz((uint32_t)(r*128+q*16));
            cpa(kb+o,      Kh_+kbase+(long)(jc*64+r)*512+q*8);
            cpa(kb+8192+o, Kl_+kbase+(long)(jc*64+r)*512+q*8);
            cpa(vb+o,      Vh_+vbase+(long)r*2048+jc*64+q*8);
            cpa(vb+8192+o, Vl_+vbase+(long)r*2048+jc*64+q*8);}
        asm volatile("cp.async.commit_group;");
    };
    // Q joins group 0
    for(int c=tid;c<1024;c+=256){int r=c>>3,q=c&7;
        cpa(sb+FQ+swz((uint32_t)(r*128+q*16)), Qh_+qoff+(long)r*512+q*8);}
    issue(0);

    int g=l>>2,t=l&3;
    int wm=(w>>1)*32, wn=(w&1)*32;
    int gr8=((l>>4)&1)*8, kch=(l>>3)&1;
    float acc_o[2][4][4]; float rsum[2][2];
    #pragma unroll
    for(int i=0;i<2;i++)
        #pragma unroll
        for(int j=0;j<4;j++)
            #pragma unroll
            for(int e=0;e<4;e++)acc_o[i][j][e]=0.f;
    rsum[0][0]=rsum[0][1]=rsum[1][0]=rsum[1][1]=0.f;

    for(int jc=0;jc<32;++jc){
        asm volatile("cp.async.wait_group 0;");    // K/V(jc) (+Q at jc=0)
        __syncthreads();                           // also: E(jc-1) consumed
        if(jc+1<32) issue(jc+1);                   // full-iteration prefetch
        uint32_t kb=sb+FK+(uint32_t)(jc&1)*16384u;
        uint32_t vb=sb+FV+(uint32_t)(jc&1)*16384u;
        // ---- sim: Qh x (Kh+Kl), K=64 ----
        float s[2][4][4];
        #pragma unroll
        for(int i=0;i<2;i++)
            #pragma unroll
            for(int j=0;j<4;j++)
                #pragma unroll
                for(int e=0;e<4;e++)s[i][j][e]=0.f;
        #pragma unroll
        for(int kk=0;kk<4;++kk){
            uint32_t fbh[4][2],fbl[4][2];
            #pragma unroll
            for(int p=0;p<2;++p){
                uint32_t ba=kb+swz((uint32_t)((wn+p*16+gr8+(l&7))*128+(kk*2+kch)*16));
                uint32_t r[4];
                ldm4(r,ba);
                fbh[2*p][0]=r[0];fbh[2*p][1]=r[1];fbh[2*p+1][0]=r[2];fbh[2*p+1][1]=r[3];
                ldm4(r,ba+8192);
                fbl[2*p][0]=r[0];fbl[2*p][1]=r[1];fbl[2*p+1][0]=r[2];fbl[2*p+1][1]=r[3];
            }
            uint32_t fa[2][4];
            #pragma unroll
            for(int mi=0;mi<2;++mi)
                ldm4(fa[mi],sb+FQ+swz((uint32_t)((wm+mi*16+(l&15))*128+(kk*2+(l>>4))*16)));
            #pragma unroll
            for(int mi=0;mi<2;++mi)
                #pragma unroll
                for(int ni=0;ni<4;++ni){
                    hmma_h(s[mi][ni],fa[mi],fbh[ni]);
                    hmma_h(s[mi][ni],fa[mi],fbl[ni]);
                }
        }
        // ---- exp -> E smem (single fp16), rowsum in regs ----
        #pragma unroll
        for(int mi=0;mi<2;++mi)
            #pragma unroll
            for(int h2=0;h2<2;++h2){
                float rp=0.f;
                int row=wm+mi*16+g+h2*8;
                #pragma unroll
                for(int ni=0;ni<4;++ni){
                    float e0=fexp(s[mi][ni][h2*2]), e1=fexp(s[mi][ni][h2*2+1]);
                    rp+=e0+e1;
                    uint32_t cb=swz((uint32_t)(row*128+(wn+ni*8+2*t)*2));
                    *(uint32_t*)(sm+FE+cb)=pk2h(__float2half(e0),__float2half(e1));
                }
                rp+=__shfl_xor_sync(0xffffffffu,rp,1);
                rp+=__shfl_xor_sync(0xffffffffu,rp,2);
                rsum[mi][h2]+=rp;
            }
        __syncthreads();                           // E visible
        // ---- out: acc_o += E @ (Vh+Vl), K=64 ----
        #pragma unroll
        for(int kk=0;kk<4;++kk){
            uint32_t gbh[4][2],gbl[4][2];
            #pragma unroll
            for(int p=0;p<2;++p){
                uint32_t ba=vb+swz((uint32_t)((wn+p*16+gr8+(l&7))*128+(kk*2+kch)*16));
                uint32_t r[4];
                ldm4(r,ba);
                gbh[2*p][0]=r[0];gbh[2*p][1]=r[1];gbh[2*p+1][0]=r[2];gbh[2*p+1][1]=r[3];
                ldm4(r,ba+8192);
                gbl[2*p][0]=r[0];gbl[2*p][1]=r[1];gbl[2*p+1][0]=r[2];gbl[2*p+1][1]=r[3];
            }
            uint32_t fe[2][4];
            #pragma unroll
            for(int mi=0;mi<2;++mi)
                ldm4(fe[mi],sb+FE+swz((uint32_t)((wm+mi*16+(l&15))*128+(kk*2+(l>>4))*16)));
            #pragma unroll
            for(int mi=0;mi<2;++mi)
                #pragma unroll
                for(int ni=0;ni<4;++ni){
                    hmma_h(acc_o[mi][ni],fe[mi],gbh[ni]);
                    hmma_h(acc_o[mi][ni],fe[mi],gbl[ni]);
                }
        }
    }
    // ---- rowsum combine, normalize, single fp16 write ----
    #pragma unroll
    for(int mi=0;mi<2;++mi)
        #pragma unroll
        for(int h2=0;h2<2;++h2)
            if(t==0) atomicAdd(srow+wm+mi*16+g+h2*8,rsum[mi][h2]);
    __syncthreads();
    #pragma unroll
    for(int mi=0;mi<2;++mi)
        #pragma unroll
        for(int h2=0;h2<2;++h2){
            int row=wm+mi*16+g+h2*8;
            float inv=1.f/srow[row];
            long a=((long)(bq*2048+i0+row))*512+hq*64+wn;
            #pragma unroll
            for(int ni=0;ni<4;++ni){
                float v0=acc_o[mi][ni][h2*2]*inv, v1=acc_o[mi][ni][h2*2+1]*inv;
                *(uint32_t*)(Oh+a+ni*8+2*t)=pk2h(__float2half(v0),__float2half(v1));
            }
        }
}

constexpr int SMBIG=49152;

extern "C" void kernel_launch(void* const* d_in,const int* in_sizes,int n_in,void* d_out,int out_size){
    (void)in_sizes;(void)n_in;(void)out_size;
    const float* x   =(const float*)d_in[0];
    const float* ctx =(const float*)d_in[1];
    const float* gx  =(const float*)d_in[2];
    const float* bx  =(const float*)d_in[3];
    const float* gc  =(const float*)d_in[4];
    const float* bc  =(const float*)d_in[5];
    const float* Wqk =(const float*)d_in[6];
    const float* Wcqk=(const float*)d_in[7];
    const float* Wv  =(const float*)d_in[8];
    const float* Wcv =(const float*)d_in[9];
    const float* Wout=(const float*)d_in[10];
    const float* bout=(const float*)d_in[11];
    const float* Wco =(const float*)d_in[12];
    const float* bco =(const float*)d_in[13];
    float* out=(float*)d_out;

    cudaFuncSetAttribute(mm_k<0>,cudaFuncAttributeMaxDynamicSharedMemorySize,SMBIG);
    cudaFuncSetAttribute(mm_k<4>,cudaFuncAttributeMaxDynamicSharedMemorySize,SMBIG);
    cudaFuncSetAttribute(fused2,cudaFuncAttributeMaxDynamicSharedMemorySize,SMF2);

    ln_k<<<MR,128>>>(x,gx,bx,0);
    ln_k<<<MR,128>>>(ctx,gc,bc,1);
    wsplit_k<<<dim3(16,16,6),dim3(32,32)>>>(Wqk,Wcqk,Wv,Wcv,Wout,Wco);
    mm_k<0><<<dim3(4,32,4),256,SMBIG>>>(nullptr,nullptr,nullptr);
    fused2<<<dim3(16,16,2),256,SMF2>>>();
    mm_k<4><<<dim3(4,32,2),256,SMBIG>>>(out,bout,bco);
}